// round 2
// baseline (speedup 1.0000x reference)
#include <cuda_runtime.h>
#include <cuda_bf16.h>
#include <math.h>

// ---------------- problem constants ----------------
#define BB 8
#define TPRE 6144
#define CIN 8
#define OUTLEN 2048
#define OUTC 8
#define AUXD 16
#define DM 256
#define DSTATE 32
#define HD 64
#define DIN 512
#define NH 8
#define CONVDIM 576
#define DPROJ 1096
#define PATCHN 16
#define NTOK 512
#define NMASK 384       // tokens >= 384 are masked
#define TFWD 512
#define TBWD 128        // backward direction truncated (only first 128 reversed tokens matter)
#define MFWD (BB*TFWD)  // 4096
#define MBWD (BB*TBWD)  // 1024

// ---------------- scratch (static device memory; no allocations) ----------------
__device__ float g_aux[BB*DM];
__device__ float g_pc[(size_t)BB*NMASK*4096];       // preconv acts in GEMM-A layout [3072, 4096]
__device__ float g_hf[(size_t)BB*NTOK*DM];          // forward stream (B,512,256)
__device__ float g_hb[(size_t)BB*TBWD*DM];          // backward stream (B,128,256)
__device__ float g_u [(size_t)MFWD*DM];
__device__ float g_zx[(size_t)MFWD*DPROJ];
__device__ float g_x [(size_t)MFWD*DIN];
__device__ float g_Bb[(size_t)MFWD*DSTATE];
__device__ float g_Cb[(size_t)MFWD*DSTATE];
__device__ float g_dt[(size_t)MFWD*NH];
__device__ float g_y [(size_t)MFWD*DIN];
__device__ float g_u2[(size_t)MFWD*DIN];

__device__ __forceinline__ float silu_f(float v) { return v / (1.0f + expf(-v)); }
__device__ __forceinline__ float softplus_f(float v) { return (v > 20.0f) ? v : log1pf(expf(v)); }

// ---------------- aux bias: silu(y_aux @ aux_w + aux_b) ----------------
__global__ void k_aux(const float* __restrict__ y_aux, const float* __restrict__ aux_w,
                      const float* __restrict__ aux_b, float* __restrict__ out) {
    __shared__ float ys[BB*AUXD];
    int c = threadIdx.x; // 256
    if (c < BB*AUXD) ys[c] = y_aux[c];
    __syncthreads();
    float wcol[AUXD];
#pragma unroll
    for (int i = 0; i < AUXD; i++) wcol[i] = aux_w[i*DM + c];
    float bias = aux_b[c];
    for (int b = 0; b < BB; b++) {
        float acc = bias;
#pragma unroll
        for (int i = 0; i < AUXD; i++) acc += ys[b*AUXD + i] * wcol[i];
        out[b*DM + c] = silu_f(acc);
    }
}

// ---------------- pre-conv (K=5, silu) -> GEMM-A layout ----------------
// block = (b, token j<384), 256 threads (one per out channel)
__global__ void k_preconv(const float* __restrict__ xp, const float* __restrict__ w,
                          const float* __restrict__ bias, float* __restrict__ pc) {
    int m = blockIdx.x;
    int b = m / NMASK, j = m % NMASK;
    int t0 = j * PATCHN;
    __shared__ float xs[20][CIN]; // positions t0-2 .. t0+17
    int tid = threadIdx.x;
    if (tid < 20*CIN) {
        int tt = t0 - 2 + tid / CIN;
        int i = tid % CIN;
        xs[tid/CIN][i] = (tt >= 0 && tt < TPRE) ? xp[((size_t)b*TPRE + tt)*CIN + i] : 0.0f;
    }
    __syncthreads();
    int c = tid;
    float wr[CIN*5];
#pragma unroll
    for (int q = 0; q < CIN*5; q++) wr[q] = w[c*CIN*5 + q];
    float bi = bias[c];
    float* outrow = pc + (size_t)m*4096 + c*PATCHN;
#pragma unroll
    for (int k = 0; k < PATCHN; k++) {
        float acc = bi;
#pragma unroll
        for (int i = 0; i < CIN; i++)
#pragma unroll
            for (int q = 0; q < 5; q++)
                acc += xs[k+q][i] * wr[i*5 + q];
        outrow[k] = silu_f(acc);
    }
}

// ---------------- generic fp32 tiled GEMM ----------------
// C[m,n] = sum_k A[m,k] * (BT ? B[n,k] : B[k,n])  (+bias[n]) (+bias2[m/rpb, n]) (+=C if ACC)
// output row mapping: C + (m/rpb)*obs + (m%rpb)*N + n
template<int BM, int BN, int BK, int TM, int TN, bool BT, bool ACC>
__global__ void k_gemm(const float* __restrict__ A, const float* __restrict__ Bm,
                       float* __restrict__ C, int M, int N, int K,
                       const float* __restrict__ bias, const float* __restrict__ bias2,
                       int rpb, long obs) {
    constexpr int THREADS = (BM/TM)*(BN/TN);
    __shared__ float As[BK][BM];
    __shared__ float Bs[BK][BN];
    int m0 = blockIdx.y * BM, n0 = blockIdx.x * BN;
    int tid = threadIdx.x;
    int tx = tid % (BN/TN), ty = tid / (BN/TN);
    float acc[TM][TN];
#pragma unroll
    for (int i = 0; i < TM; i++)
#pragma unroll
        for (int j = 0; j < TN; j++) acc[i][j] = 0.0f;

    for (int k0 = 0; k0 < K; k0 += BK) {
        // A tile (float4 along K; K is a multiple of BK=8 for all call sites)
        {
            constexpr int NF4 = BM*BK/4;
            for (int i = tid; i < NF4; i += THREADS) {
                int r = i / (BK/4);
                int c4 = (i % (BK/4)) * 4;
                float4 v = make_float4(0,0,0,0);
                if (m0 + r < M) v = *reinterpret_cast<const float4*>(A + (size_t)(m0+r)*K + k0 + c4);
                As[c4+0][r] = v.x; As[c4+1][r] = v.y; As[c4+2][r] = v.z; As[c4+3][r] = v.w;
            }
        }
        if (!BT) {
            constexpr int NF4 = BK*BN/4;
            for (int i = tid; i < NF4; i += THREADS) {
                int r = i / (BN/4);
                int c4 = (i % (BN/4)) * 4;
                float4 v = make_float4(0,0,0,0);
                if (n0 + c4 < N) v = *reinterpret_cast<const float4*>(Bm + (size_t)(k0+r)*N + n0 + c4);
                *reinterpret_cast<float4*>(&Bs[r][c4]) = v;
            }
        } else {
            constexpr int NF4 = BN*BK/4;
            for (int i = tid; i < NF4; i += THREADS) {
                int n = i / (BK/4);
                int c4 = (i % (BK/4)) * 4;
                float4 v = make_float4(0,0,0,0);
                if (n0 + n < N) v = *reinterpret_cast<const float4*>(Bm + (size_t)(n0+n)*K + k0 + c4);
                Bs[c4+0][n] = v.x; Bs[c4+1][n] = v.y; Bs[c4+2][n] = v.z; Bs[c4+3][n] = v.w;
            }
        }
        __syncthreads();
#pragma unroll
        for (int k = 0; k < BK; k++) {
            float a[TM], bb[TN];
#pragma unroll
            for (int i = 0; i < TM; i += 4)
                *reinterpret_cast<float4*>(&a[i]) = *reinterpret_cast<const float4*>(&As[k][ty*TM + i]);
#pragma unroll
            for (int j = 0; j < TN; j += 4)
                *reinterpret_cast<float4*>(&bb[j]) = *reinterpret_cast<const float4*>(&Bs[k][tx*TN + j]);
#pragma unroll
            for (int i = 0; i < TM; i++)
#pragma unroll
                for (int j = 0; j < TN; j++)
                    acc[i][j] = fmaf(a[i], bb[j], acc[i][j]);
        }
        __syncthreads();
    }
#pragma unroll
    for (int i = 0; i < TM; i++) {
        int m = m0 + ty*TM + i;
        if (m >= M) continue;
        int bidx = m / rpb;
        int mr = m % rpb;
        float* crow = C + (size_t)bidx*obs + (size_t)mr*N;
#pragma unroll
        for (int j = 0; j < TN; j++) {
            int n = n0 + tx*TN + j;
            if (n >= N) continue;
            float v = acc[i][j];
            if (bias)  v += bias[n];
            if (bias2) v += bias2[bidx*N + n];
            if (ACC) crow[n] += v; else crow[n] = v;
        }
    }
}

// ---------------- fill masked tokens: h_f[384:512] and all of h_b ----------------
__global__ void k_maskfill(const float* __restrict__ mask_token, const float* __restrict__ aux,
                           float* __restrict__ hf, float* __restrict__ hb) {
    int idx = blockIdx.x * blockDim.x + threadIdx.x;
    if (idx >= BB*TBWD*DM) return;
    int c = idx % DM;
    int j = (idx / DM) % TBWD;
    int b = idx / (DM*TBWD);
    float v = mask_token[c] + aux[b*DM + c];
    hf[((size_t)b*NTOK + NMASK + j)*DM + c] = v;
    hb[((size_t)b*TBWD + j)*DM + c] = v;
}

// ---------------- rmsnorm over C channels ----------------
template<int C>
__global__ void k_rmsnorm(const float* __restrict__ in, const float* __restrict__ w,
                          float* __restrict__ out) {
    int m = blockIdx.x;
    int c = threadIdx.x;
    float v = in[(size_t)m*C + c];
    float s = v*v;
#pragma unroll
    for (int o = 16; o > 0; o >>= 1) s += __shfl_xor_sync(0xffffffffu, s, o);
    __shared__ float ws[C/32];
    if ((c & 31) == 0) ws[c >> 5] = s;
    __syncthreads();
    float tot = 0.0f;
#pragma unroll
    for (int i = 0; i < C/32; i++) tot += ws[i];
    float rs = rsqrtf(tot / (float)C + 1e-5f);
    out[(size_t)m*C + c] = v * rs * w[c];
}

// ---------------- depthwise causal conv (K=4) + silu + dt softplus ----------------
__global__ void k_convdt(const float* __restrict__ zx, const float* __restrict__ cw,
                         const float* __restrict__ cb, const float* __restrict__ dtbias,
                         float* __restrict__ X, float* __restrict__ Bo, float* __restrict__ Co,
                         float* __restrict__ dto, int T) {
    int m = blockIdx.x;
    int b = m / T, t = m % T;
    int c = threadIdx.x; // 576
    float acc = cb[c];
    const float* w4 = cw + c*4;
#pragma unroll
    for (int q = 0; q < 4; q++) {
        int tt = t - 3 + q;
        if (tt >= 0) acc += zx[((size_t)(b*T + tt))*DPROJ + DIN + c] * w4[q];
    }
    float v = silu_f(acc);
    if (c < DIN)            X[(size_t)m*DIN + c] = v;
    else if (c < DIN+DSTATE) Bo[m*DSTATE + (c-DIN)] = v;
    else                     Co[m*DSTATE + (c-DIN-DSTATE)] = v;
    if (c < NH) dto[m*NH + c] = softplus_f(zx[(size_t)m*DPROJ + 2*DIN + 2*DSTATE + c] + dtbias[c]);
}

// ---------------- sequential SSM scan ----------------
// grid = B*NH (64 blocks), block = 1024 = 32 warps; warp w -> p in {2w, 2w+1}; lane = state dim n
__global__ void __launch_bounds__(1024, 1)
k_scan(const float* __restrict__ X, const float* __restrict__ Bb, const float* __restrict__ Cb,
       const float* __restrict__ dtb, const float* __restrict__ Alog, const float* __restrict__ Dp,
       float* __restrict__ Y, int T) {
    int bh = blockIdx.x;
    int b = bh >> 3, h = bh & 7;
    int w = threadIdx.x >> 5, lane = threadIdx.x & 31;
    int p0 = w * 2;
    float A  = -expf(Alog[h]);
    float Dh = Dp[h];
    float h0 = 0.0f, h1 = 0.0f;
    for (int t = 0; t < T; t++) {
        int base = b*T + t;
        float dt = dtb[base*NH + h];
        float Bn = Bb[base*DSTATE + lane];
        float Cn = Cb[base*DSTATE + lane];
        float x0 = X[(size_t)base*DIN + h*HD + p0];
        float x1 = X[(size_t)base*DIN + h*HD + p0 + 1];
        float dA = expf(dt * A);
        h0 = h0*dA + (dt*x0)*Bn;
        h1 = h1*dA + (dt*x1)*Bn;
        float y0 = h0*Cn, y1 = h1*Cn;
#pragma unroll
        for (int o = 16; o > 0; o >>= 1) {
            y0 += __shfl_xor_sync(0xffffffffu, y0, o);
            y1 += __shfl_xor_sync(0xffffffffu, y1, o);
        }
        if (lane == 0) {
            Y[(size_t)base*DIN + h*HD + p0]     = y0 + Dh*x0;
            Y[(size_t)base*DIN + h*HD + p0 + 1] = y1 + Dh*x1;
        }
    }
}

// ---------------- gated rmsnorm: rmsnorm(Y * silu(z)) * gnorm ----------------
__global__ void k_gatednorm(const float* __restrict__ Y, const float* __restrict__ zx,
                            const float* __restrict__ gw, float* __restrict__ out) {
    int m = blockIdx.x;
    int c = threadIdx.x; // 512
    float z = zx[(size_t)m*DPROJ + c];
    float g = Y[(size_t)m*DIN + c] * silu_f(z);
    float s = g*g;
#pragma unroll
    for (int o = 16; o > 0; o >>= 1) s += __shfl_xor_sync(0xffffffffu, s, o);
    __shared__ float ws[16];
    if ((c & 31) == 0) ws[c >> 5] = s;
    __syncthreads();
    float tot = 0.0f;
#pragma unroll
    for (int i = 0; i < 16; i++) tot += ws[i];
    float rs = rsqrtf(tot / (float)DIN + 1e-5f);
    out[(size_t)m*DIN + c] = g * rs * gw[c];
}

// ---------------- final: concat [h_f, rev(h_b)] @ patch_out_w + b ----------------
// The reference's double reshape (b,nt,OUT_C,PATCH)->(b,nt*PATCH,OUT_C) is a FLAT
// reinterpretation: per-token 128-vector element k lands at flat out offset j*128+k.
// grid = B*128 (tokens 384..511), block 128
__global__ void k_final(const float* __restrict__ hf, const float* __restrict__ hb,
                        const float* __restrict__ W, const float* __restrict__ bias,
                        float* __restrict__ out) {
    int blk = blockIdx.x;
    int b = blk >> 7, jj = blk & 127;
    int j = NMASK + jj;
    __shared__ float row[2*DM];
    int tid = threadIdx.x; // 128
    row[tid]       = hf[((size_t)b*NTOK + j)*DM + tid];
    row[tid + 128] = hf[((size_t)b*NTOK + j)*DM + tid + 128];
    int jb = (NTOK - 1) - j; // in [0,128)
    row[256 + tid] = hb[((size_t)b*TBWD + jb)*DM + tid];
    row[384 + tid] = hb[((size_t)b*TBWD + jb)*DM + tid + 128];
    __syncthreads();
    float acc = bias[tid];
#pragma unroll 8
    for (int k = 0; k < 2*DM; k++) acc += row[k] * W[k*128 + tid];
    out[(size_t)b*OUTLEN*OUTC + jj*128 + tid] = acc;
}

// ================= host =================
extern "C" void kernel_launch(void* const* d_in, const int* in_sizes, int n_in,
                              void* d_out, int out_size) {
    // resolve scratch
    float *aux, *pc, *hf, *hb, *u, *zx, *X, *Bb, *Cb, *dt, *Y, *u2;
    cudaGetSymbolAddress((void**)&aux, g_aux);
    cudaGetSymbolAddress((void**)&pc,  g_pc);
    cudaGetSymbolAddress((void**)&hf,  g_hf);
    cudaGetSymbolAddress((void**)&hb,  g_hb);
    cudaGetSymbolAddress((void**)&u,   g_u);
    cudaGetSymbolAddress((void**)&zx,  g_zx);
    cudaGetSymbolAddress((void**)&X,   g_x);
    cudaGetSymbolAddress((void**)&Bb,  g_Bb);
    cudaGetSymbolAddress((void**)&Cb,  g_Cb);
    cudaGetSymbolAddress((void**)&dt,  g_dt);
    cudaGetSymbolAddress((void**)&Y,   g_y);
    cudaGetSymbolAddress((void**)&u2,  g_u2);

    const float* x_prefix   = (const float*)d_in[0];
    const float* y_aux      = (const float*)d_in[1];
    const float* pre_conv_w = (const float*)d_in[2];
    const float* pre_conv_b = (const float*)d_in[3];
    const float* patch_w    = (const float*)d_in[4];
    const float* patch_b    = (const float*)d_in[5];
    const float* mask_token = (const float*)d_in[6];
    const float* aux_w      = (const float*)d_in[7];
    const float* aux_b      = (const float*)d_in[8];

    // input ordering: setup_inputs dict order puts patch_out_w (65536 elems) at idx 9;
    // reference-signature order puts fwd_norm_w (512) there.
    const float *patch_out_w, *patch_out_b;
    int fbase, bbase;
    if (n_in > 9 && in_sizes[9] == 65536) {
        patch_out_w = (const float*)d_in[9];
        patch_out_b = (const float*)d_in[10];
        fbase = 11; bbase = 20;
    } else {
        fbase = 9; bbase = 18;
        patch_out_w = (const float*)d_in[27];
        patch_out_b = (const float*)d_in[28];
    }

    // stage 0/1: aux bias, preconv, patch GEMM, mask fill
    k_aux<<<1, 256>>>(y_aux, aux_w, aux_b, aux);
    k_preconv<<<BB*NMASK, 256>>>(x_prefix, pre_conv_w, pre_conv_b, pc);
    {
        dim3 grid((DM + 63) / 64, (BB*NMASK) / 128);
        k_gemm<128,64,8,8,4,true,false><<<grid, 256>>>(
            pc, patch_w, hf, BB*NMASK, DM, 4096, patch_b, aux, NMASK, (long)NTOK*DM);
    }
    k_maskfill<<<(BB*TBWD*DM + 255)/256, 256>>>(mask_token, aux, hf, hb);

    for (int dir = 0; dir < 2; dir++) {
        int base = dir ? bbase : fbase;
        const float* norm_w  = (const float*)d_in[base + 0];
        const float* inproj  = (const float*)d_in[base + 1];
        const float* conv_w  = (const float*)d_in[base + 2];
        const float* conv_b  = (const float*)d_in[base + 3];
        const float* dtbias  = (const float*)d_in[base + 4];
        const float* Alog    = (const float*)d_in[base + 5];
        const float* Dvec    = (const float*)d_in[base + 6];
        const float* gnorm   = (const float*)d_in[base + 7];
        const float* outproj = (const float*)d_in[base + 8];
        float* h = dir ? hb : hf;
        int T = dir ? TBWD : TFWD;
        int M = BB * T;

        for (int lay = 0; lay < 2; lay++) {
            k_rmsnorm<DM><<<M, DM>>>(h, norm_w + lay*DM, u);
            {
                dim3 grid((DPROJ + 63) / 64, M / 128);
                k_gemm<128,64,8,8,4,false,false><<<grid, 256>>>(
                    u, inproj + (size_t)lay*DM*DPROJ, zx, M, DPROJ, DM,
                    nullptr, nullptr, M, 0L);
            }
            k_convdt<<<M, CONVDIM>>>(zx, conv_w + lay*CONVDIM*4, conv_b + lay*CONVDIM,
                                     dtbias + lay*NH, X, Bb, Cb, dt, T);
            k_scan<<<BB*NH, 1024>>>(X, Bb, Cb, dt, Alog + lay*NH, Dvec + lay*NH, Y, T);
            k_gatednorm<<<M, DIN>>>(Y, zx, gnorm + lay*DIN, u2);
            {
                dim3 grid((DM + 63) / 64, M / 128);
                k_gemm<128,64,8,8,4,false,true><<<grid, 256>>>(
                    u2, outproj + (size_t)lay*DIN*DM, h, M, DM, DIN,
                    nullptr, nullptr, M, 0L);
            }
        }
    }

    k_final<<<BB*TBWD, 128>>>(hf, hb, patch_out_w, patch_out_b, (float*)d_out);
    (void)in_sizes; (void)n_in; (void)out_size;
}

// round 4
// speedup vs baseline: 1.5660x; 1.5660x over previous
#include <cuda_runtime.h>
#include <cuda_bf16.h>
#include <math.h>

// ---------------- problem constants ----------------
#define BB 8
#define TPRE 6144
#define CIN 8
#define OUTLEN 2048
#define OUTC 8
#define AUXD 16
#define DM 256
#define DSTATE 32
#define HD 64
#define DIN 512
#define NH 8
#define CONVDIM 576
#define DPROJ 1096
#define PATCHN 16
#define NTOK 512
#define NMASK 384       // tokens >= 384 are masked
#define TFWD 512
#define TBWD 128        // backward direction truncated
#define MFWD (BB*TFWD)  // 4096
#define MBWD (BB*TBWD)  // 1024
#define MTOT (MFWD+MBWD) // 5120
#define KSPLIT 4
#define KCHUNK 1024

// ---------------- scratch ----------------
__device__ float g_aux[BB*DM];
__device__ float g_pc[(size_t)BB*NMASK*4096];
__device__ float g_pp[(size_t)KSPLIT*BB*NMASK*DM];   // split-K partials
__device__ float g_hf[(size_t)BB*NTOK*DM];
__device__ float g_hb[(size_t)BB*TBWD*DM];
__device__ float g_u [(size_t)MTOT*DM];
__device__ float g_zx[(size_t)MTOT*DPROJ];
__device__ float g_x [(size_t)MTOT*DIN];
__device__ float g_Bb[(size_t)MTOT*DSTATE];
__device__ float g_Cb[(size_t)MTOT*DSTATE];
__device__ float g_dt[(size_t)MTOT*NH];
__device__ float g_y [(size_t)MTOT*DIN];
__device__ float g_u2[(size_t)MTOT*DIN];

__device__ __forceinline__ float silu_f(float v) { return v / (1.0f + expf(-v)); }
__device__ __forceinline__ float softplus_f(float v) { return (v > 20.0f) ? v : log1pf(expf(v)); }

__device__ __forceinline__ float warp_sum(float v) {
#pragma unroll
    for (int o = 16; o > 0; o >>= 1) v += __shfl_xor_sync(0xffffffffu, v, o);
    return v;
}

// ---------------- aux bias ----------------
__global__ void k_aux(const float* __restrict__ y_aux, const float* __restrict__ aux_w,
                      const float* __restrict__ aux_b, float* __restrict__ out) {
    __shared__ float ys[BB*AUXD];
    int c = threadIdx.x; // 256
    if (c < BB*AUXD) ys[c] = y_aux[c];
    __syncthreads();
    float wcol[AUXD];
#pragma unroll
    for (int i = 0; i < AUXD; i++) wcol[i] = aux_w[i*DM + c];
    float bias = aux_b[c];
    for (int b = 0; b < BB; b++) {
        float acc = bias;
#pragma unroll
        for (int i = 0; i < AUXD; i++) acc += ys[b*AUXD + i] * wcol[i];
        out[b*DM + c] = silu_f(acc);
    }
}

// ---------------- pre-conv ----------------
__global__ void k_preconv(const float* __restrict__ xp, const float* __restrict__ w,
                          const float* __restrict__ bias, float* __restrict__ pc) {
    int m = blockIdx.x;
    int b = m / NMASK, j = m % NMASK;
    int t0 = j * PATCHN;
    __shared__ float xs[20][CIN];
    int tid = threadIdx.x;
    if (tid < 20*CIN) {
        int tt = t0 - 2 + tid / CIN;
        int i = tid % CIN;
        xs[tid/CIN][i] = (tt >= 0 && tt < TPRE) ? xp[((size_t)b*TPRE + tt)*CIN + i] : 0.0f;
    }
    __syncthreads();
    int c = tid;
    float wr[CIN*5];
#pragma unroll
    for (int q = 0; q < CIN*5; q++) wr[q] = w[c*CIN*5 + q];
    float bi = bias[c];
    float* outrow = pc + (size_t)m*4096 + c*PATCHN;
#pragma unroll
    for (int k = 0; k < PATCHN; k++) {
        float acc = bi;
#pragma unroll
        for (int i = 0; i < CIN; i++)
#pragma unroll
            for (int q = 0; q < 5; q++)
                acc += xs[k+q][i] * wr[i*5 + q];
        outrow[k] = silu_f(acc);
    }
}

// ---------------- patch GEMM, split-K, B transposed ----------------
template<int BM, int BN, int BK, int TM, int TN>
__global__ void k_gemm_patch(const float* __restrict__ A, const float* __restrict__ Bm,
                             float* __restrict__ C, int M, int N, int Kfull) {
    constexpr int THREADS = (BM/TM)*(BN/TN);
    __shared__ float As[BK][BM];
    __shared__ float Bs[BK][BN];
    int m0 = blockIdx.y * BM, n0 = blockIdx.x * BN;
    int kstart = blockIdx.z * KCHUNK;
    C += (size_t)blockIdx.z * M * N;
    int tid = threadIdx.x;
    int tx = tid % (BN/TN), ty = tid / (BN/TN);
    float acc[TM][TN];
#pragma unroll
    for (int i = 0; i < TM; i++)
#pragma unroll
        for (int j = 0; j < TN; j++) acc[i][j] = 0.0f;

    for (int k0 = 0; k0 < KCHUNK; k0 += BK) {
        {
            constexpr int NF4 = BM*BK/4;
#pragma unroll
            for (int i = tid; i < NF4; i += THREADS) {
                int r = i / (BK/4);
                int c4 = (i % (BK/4)) * 4;
                float4 v = *reinterpret_cast<const float4*>(A + (size_t)(m0+r)*Kfull + kstart + k0 + c4);
                As[c4+0][r] = v.x; As[c4+1][r] = v.y; As[c4+2][r] = v.z; As[c4+3][r] = v.w;
            }
        }
        {
            constexpr int NF4 = BN*BK/4;
#pragma unroll
            for (int i = tid; i < NF4; i += THREADS) {
                int n = i / (BK/4);
                int c4 = (i % (BK/4)) * 4;
                float4 v = *reinterpret_cast<const float4*>(Bm + (size_t)(n0+n)*Kfull + kstart + k0 + c4);
                Bs[c4+0][n] = v.x; Bs[c4+1][n] = v.y; Bs[c4+2][n] = v.z; Bs[c4+3][n] = v.w;
            }
        }
        __syncthreads();
#pragma unroll
        for (int k = 0; k < BK; k++) {
            float a[TM], bb[TN];
#pragma unroll
            for (int i = 0; i < TM; i += 4)
                *reinterpret_cast<float4*>(&a[i]) = *reinterpret_cast<const float4*>(&As[k][ty*TM + i]);
#pragma unroll
            for (int j = 0; j < TN; j += 4)
                *reinterpret_cast<float4*>(&bb[j]) = *reinterpret_cast<const float4*>(&Bs[k][tx*TN + j]);
#pragma unroll
            for (int i = 0; i < TM; i++)
#pragma unroll
                for (int j = 0; j < TN; j++)
                    acc[i][j] = fmaf(a[i], bb[j], acc[i][j]);
        }
        __syncthreads();
    }
#pragma unroll
    for (int i = 0; i < TM; i++) {
        int m = m0 + ty*TM + i;
        float* crow = C + (size_t)m*N;
#pragma unroll
        for (int j = 0; j < TN; j++) {
            int n = n0 + tx*TN + j;
            crow[n] = acc[i][j];
        }
    }
}

// reduce split-K partials + bias + aux -> hf
__global__ void k_patchreduce(const float* __restrict__ pp, const float* __restrict__ bias,
                              const float* __restrict__ aux, float* __restrict__ hf) {
    int idx = blockIdx.x * blockDim.x + threadIdx.x; // over 3072*256
    int m = idx >> 8, n = idx & 255;
    float v = bias[n];
#pragma unroll
    for (int z = 0; z < KSPLIT; z++) v += pp[(size_t)z*BB*NMASK*DM + idx];
    int b = m / NMASK, j = m % NMASK;
    hf[((size_t)b*NTOK + j)*DM + n] = v + aux[b*DM + n];
}

// ---------------- dual-direction GEMM (B not transposed) ----------------
template<int BM, int BN, int BK, int TM, int TN, bool ACC, bool SPLITC>
__global__ void k_gemm2(const float* __restrict__ A, const float* __restrict__ Bf,
                        const float* __restrict__ Bbw, float* __restrict__ Cf,
                        float* __restrict__ Cb, int N, int K) {
    constexpr int THREADS = (BM/TM)*(BN/TN);
    __shared__ float As[BK][BM];
    __shared__ float Bs[BK][BN];
    int m0 = blockIdx.y * BM, n0 = blockIdx.x * BN;
    const float* Bm = (m0 >= MFWD) ? Bbw : Bf;
    int tid = threadIdx.x;
    int tx = tid % (BN/TN), ty = tid / (BN/TN);
    float acc[TM][TN];
#pragma unroll
    for (int i = 0; i < TM; i++)
#pragma unroll
        for (int j = 0; j < TN; j++) acc[i][j] = 0.0f;

    for (int k0 = 0; k0 < K; k0 += BK) {
        {
            constexpr int NF4 = BM*BK/4;
#pragma unroll
            for (int i = tid; i < NF4; i += THREADS) {
                int r = i / (BK/4);
                int c4 = (i % (BK/4)) * 4;
                float4 v = *reinterpret_cast<const float4*>(A + (size_t)(m0+r)*K + k0 + c4);
                As[c4+0][r] = v.x; As[c4+1][r] = v.y; As[c4+2][r] = v.z; As[c4+3][r] = v.w;
            }
        }
        {
            constexpr int NF4 = BK*BN/4;
#pragma unroll
            for (int i = tid; i < NF4; i += THREADS) {
                int r = i / (BN/4);
                int c4 = (i % (BN/4)) * 4;
                float4 v = make_float4(0,0,0,0);
                if (n0 + c4 < N) v = *reinterpret_cast<const float4*>(Bm + (size_t)(k0+r)*N + n0 + c4);
                *reinterpret_cast<float4*>(&Bs[r][c4]) = v;
            }
        }
        __syncthreads();
#pragma unroll
        for (int k = 0; k < BK; k++) {
            float a[TM], bb[TN];
#pragma unroll
            for (int i = 0; i < TM; i += 4)
                *reinterpret_cast<float4*>(&a[i]) = *reinterpret_cast<const float4*>(&As[k][ty*TM + i]);
#pragma unroll
            for (int j = 0; j < TN; j += 4)
                *reinterpret_cast<float4*>(&bb[j]) = *reinterpret_cast<const float4*>(&Bs[k][tx*TN + j]);
#pragma unroll
            for (int i = 0; i < TM; i++)
#pragma unroll
                for (int j = 0; j < TN; j++)
                    acc[i][j] = fmaf(a[i], bb[j], acc[i][j]);
        }
        __syncthreads();
    }
#pragma unroll
    for (int i = 0; i < TM; i++) {
        int m = m0 + ty*TM + i;
        float* crow;
        if (SPLITC) crow = (m < MFWD) ? (Cf + (size_t)m*N) : (Cb + (size_t)(m-MFWD)*N);
        else        crow = Cf + (size_t)m*N;
#pragma unroll
        for (int j = 0; j < TN; j++) {
            int n = n0 + tx*TN + j;
            if (n >= N) continue;
            if (ACC) crow[n] += acc[i][j]; else crow[n] = acc[i][j];
        }
    }
}

// ---------------- mask fill ----------------
__global__ void k_maskfill(const float* __restrict__ mask_token, const float* __restrict__ aux,
                           float* __restrict__ hf, float* __restrict__ hb) {
    int idx = blockIdx.x * blockDim.x + threadIdx.x;
    if (idx >= BB*TBWD*DM) return;
    int c = idx % DM;
    int j = (idx / DM) % TBWD;
    int b = idx / (DM*TBWD);
    float v = mask_token[c] + aux[b*DM + c];
    hf[((size_t)b*NTOK + NMASK + j)*DM + c] = v;
    hb[((size_t)b*TBWD + j)*DM + c] = v;
}

// ---------------- combined rmsnorm (256 ch) ----------------
__global__ void k_rmsnorm2(const float* __restrict__ hf, const float* __restrict__ hb,
                           const float* __restrict__ wf, const float* __restrict__ wb,
                           float* __restrict__ out) {
    int m = blockIdx.x; // [0, MTOT)
    int c = threadIdx.x; // 256
    const float* in = (m < MFWD) ? (hf + (size_t)m*DM) : (hb + (size_t)(m-MFWD)*DM);
    const float* w  = (m < MFWD) ? wf : wb;
    float v = in[c];
    float s = warp_sum(v*v);
    __shared__ float ws[8];
    if ((c & 31) == 0) ws[c >> 5] = s;
    __syncthreads();
    float tot = 0.0f;
#pragma unroll
    for (int i = 0; i < 8; i++) tot += ws[i];
    float rs = rsqrtf(tot / (float)DM + 1e-5f);
    out[(size_t)m*DM + c] = v * rs * w[c];
}

// ---------------- combined conv + dt ----------------
__global__ void k_convdt2(const float* __restrict__ zx,
                          const float* __restrict__ cwf, const float* __restrict__ cbf,
                          const float* __restrict__ dtbf,
                          const float* __restrict__ cwb, const float* __restrict__ cbb,
                          const float* __restrict__ dtbb,
                          float* __restrict__ X, float* __restrict__ Bo, float* __restrict__ Co,
                          float* __restrict__ dto) {
    int m = blockIdx.x; // [0, MTOT)
    int c = threadIdx.x; // 576
    int t;
    const float *cw, *cb, *dtb;
    if (m < MFWD) { t = m & (TFWD-1); cw = cwf; cb = cbf; dtb = dtbf; }
    else          { t = (m - MFWD) & (TBWD-1); cw = cwb; cb = cbb; dtb = dtbb; }
    float acc = cb[c];
    const float* w4 = cw + c*4;
#pragma unroll
    for (int q = 0; q < 4; q++) {
        int tt = t - 3 + q;
        if (tt >= 0) acc += zx[((size_t)(m - 3 + q))*DPROJ + DIN + c] * w4[q];
    }
    float v = silu_f(acc);
    if (c < DIN)             X[(size_t)m*DIN + c] = v;
    else if (c < DIN+DSTATE) Bo[m*DSTATE + (c-DIN)] = v;
    else                     Co[m*DSTATE + (c-DIN-DSTATE)] = v;
    if (c < NH) dto[m*NH + c] = softplus_f(zx[(size_t)m*DPROJ + 2*DIN + 2*DSTATE + c] + dtb[c]);
}

// ---------------- combined scan ----------------
// grid = 128: blocks [0,64) fwd (T=512), [64,128) bwd (T=128)
__global__ void __launch_bounds__(1024, 1)
k_scan2(const float* __restrict__ X, const float* __restrict__ Bb, const float* __restrict__ Cb,
        const float* __restrict__ dtb,
        const float* __restrict__ Alogf, const float* __restrict__ Dpf,
        const float* __restrict__ Alogb, const float* __restrict__ Dpb) {
    float* __restrict__ Y = g_y;
    int blk = blockIdx.x;
    int T, rowbase, h;
    float A, Dh;
    if (blk < 64) {
        int b = blk >> 3; h = blk & 7;
        T = TFWD; rowbase = b * TFWD;
        A = -expf(Alogf[h]); Dh = Dpf[h];
    } else {
        int b = (blk - 64) >> 3; h = blk & 7;
        T = TBWD; rowbase = MFWD + b * TBWD;
        A = -expf(Alogb[h]); Dh = Dpb[h];
    }
    int w = threadIdx.x >> 5, lane = threadIdx.x & 31;
    int p0 = w * 2;
    float h0 = 0.0f, h1 = 0.0f;
    for (int t = 0; t < T; t++) {
        int r = rowbase + t;
        float dt = dtb[r*NH + h];
        float Bn = Bb[r*DSTATE + lane];
        float Cn = Cb[r*DSTATE + lane];
        float x0 = X[(size_t)r*DIN + h*HD + p0];
        float x1 = X[(size_t)r*DIN + h*HD + p0 + 1];
        float dA = expf(dt * A);
        h0 = h0*dA + (dt*x0)*Bn;
        h1 = h1*dA + (dt*x1)*Bn;
        float y0 = h0*Cn, y1 = h1*Cn;
#pragma unroll
        for (int o = 16; o > 0; o >>= 1) {
            y0 += __shfl_xor_sync(0xffffffffu, y0, o);
            y1 += __shfl_xor_sync(0xffffffffu, y1, o);
        }
        if (lane == 0) {
            Y[(size_t)r*DIN + h*HD + p0]     = y0 + Dh*x0;
            Y[(size_t)r*DIN + h*HD + p0 + 1] = y1 + Dh*x1;
        }
    }
}

// ---------------- combined gated rmsnorm ----------------
__global__ void k_gatednorm2(const float* __restrict__ Y, const float* __restrict__ zx,
                             const float* __restrict__ gwf, const float* __restrict__ gwb,
                             float* __restrict__ out) {
    int m = blockIdx.x; // MTOT
    int c = threadIdx.x; // 512
    const float* gw = (m < MFWD) ? gwf : gwb;
    float z = zx[(size_t)m*DPROJ + c];
    float g = Y[(size_t)m*DIN + c] * silu_f(z);
    float s = warp_sum(g*g);
    __shared__ float ws[16];
    if ((c & 31) == 0) ws[c >> 5] = s;
    __syncthreads();
    float tot = 0.0f;
#pragma unroll
    for (int i = 0; i < 16; i++) tot += ws[i];
    float rs = rsqrtf(tot / (float)DIN + 1e-5f);
    out[(size_t)m*DIN + c] = g * rs * gw[c];
}

// ---------------- final projection + flat scatter ----------------
__global__ void k_final(const float* __restrict__ hf, const float* __restrict__ hb,
                        const float* __restrict__ W, const float* __restrict__ bias,
                        float* __restrict__ out) {
    int blk = blockIdx.x;
    int b = blk >> 7, jj = blk & 127;
    int j = NMASK + jj;
    __shared__ float row[2*DM];
    int tid = threadIdx.x; // 128
    row[tid]       = hf[((size_t)b*NTOK + j)*DM + tid];
    row[tid + 128] = hf[((size_t)b*NTOK + j)*DM + tid + 128];
    int jb = (NTOK - 1) - j;
    row[256 + tid] = hb[((size_t)b*TBWD + jb)*DM + tid];
    row[384 + tid] = hb[((size_t)b*TBWD + jb)*DM + tid + 128];
    __syncthreads();
    float acc = bias[tid];
#pragma unroll 8
    for (int k = 0; k < 2*DM; k++) acc += row[k] * W[k*128 + tid];
    out[(size_t)b*OUTLEN*OUTC + jj*128 + tid] = acc;
}

// ================= host =================
extern "C" void kernel_launch(void* const* d_in, const int* in_sizes, int n_in,
                              void* d_out, int out_size) {
    float *aux, *pc, *pp, *hf, *hb, *u, *zx, *X, *Bbuf, *Cbuf, *dt, *Y, *u2;
    cudaGetSymbolAddress((void**)&aux, g_aux);
    cudaGetSymbolAddress((void**)&pc,  g_pc);
    cudaGetSymbolAddress((void**)&pp,  g_pp);
    cudaGetSymbolAddress((void**)&hf,  g_hf);
    cudaGetSymbolAddress((void**)&hb,  g_hb);
    cudaGetSymbolAddress((void**)&u,   g_u);
    cudaGetSymbolAddress((void**)&zx,  g_zx);
    cudaGetSymbolAddress((void**)&X,   g_x);
    cudaGetSymbolAddress((void**)&Bbuf, g_Bb);
    cudaGetSymbolAddress((void**)&Cbuf, g_Cb);
    cudaGetSymbolAddress((void**)&dt,  g_dt);
    cudaGetSymbolAddress((void**)&Y,   g_y);
    cudaGetSymbolAddress((void**)&u2,  g_u2);

    const float* x_prefix   = (const float*)d_in[0];
    const float* y_aux      = (const float*)d_in[1];
    const float* pre_conv_w = (const float*)d_in[2];
    const float* pre_conv_b = (const float*)d_in[3];
    const float* patch_w    = (const float*)d_in[4];
    const float* patch_b    = (const float*)d_in[5];
    const float* mask_token = (const float*)d_in[6];
    const float* aux_w      = (const float*)d_in[7];
    const float* aux_b      = (const float*)d_in[8];

    const float *patch_out_w, *patch_out_b;
    int fbase, bbase;
    if (n_in > 9 && in_sizes[9] == 65536) {
        patch_out_w = (const float*)d_in[9];
        patch_out_b = (const float*)d_in[10];
        fbase = 11; bbase = 20;
    } else {
        fbase = 9; bbase = 18;
        patch_out_w = (const float*)d_in[27];
        patch_out_b = (const float*)d_in[28];
    }

    const float* fW[9]; const float* bW[9];
    for (int i = 0; i < 9; i++) { fW[i] = (const float*)d_in[fbase+i]; bW[i] = (const float*)d_in[bbase+i]; }
    // 0:norm_w 1:inproj 2:conv_w 3:conv_b 4:dtbias 5:Alog 6:D 7:gnorm 8:outproj

    k_aux<<<1, 256>>>(y_aux, aux_w, aux_b, aux);
    k_preconv<<<BB*NMASK, 256>>>(x_prefix, pre_conv_w, pre_conv_b, pc);
    {
        dim3 grid(DM/64, (BB*NMASK)/128, KSPLIT);
        k_gemm_patch<128,64,16,8,4><<<grid, 256>>>(pc, patch_w, pp, BB*NMASK, DM, 4096);
    }
    k_patchreduce<<<(BB*NMASK*DM)/256, 256>>>(pp, patch_b, aux, hf);
    k_maskfill<<<(BB*TBWD*DM + 255)/256, 256>>>(mask_token, aux, hf, hb);

    for (int lay = 0; lay < 2; lay++) {
        k_rmsnorm2<<<MTOT, DM>>>(hf, hb, fW[0] + lay*DM, bW[0] + lay*DM, u);
        {
            dim3 grid((DPROJ + 63)/64, MTOT/128);
            k_gemm2<128,64,16,8,4,false,false><<<grid, 256>>>(
                u, fW[1] + (size_t)lay*DM*DPROJ, bW[1] + (size_t)lay*DM*DPROJ,
                zx, nullptr, DPROJ, DM);
        }
        k_convdt2<<<MTOT, CONVDIM>>>(zx,
            fW[2] + lay*CONVDIM*4, fW[3] + lay*CONVDIM, fW[4] + lay*NH,
            bW[2] + lay*CONVDIM*4, bW[3] + lay*CONVDIM, bW[4] + lay*NH,
            X, Bbuf, Cbuf, dt);
        k_scan2<<<128, 1024>>>(X, Bbuf, Cbuf, dt,
            fW[5] + lay*NH, fW[6] + lay*NH, bW[5] + lay*NH, bW[6] + lay*NH);
        k_gatednorm2<<<MTOT, DIN>>>(Y, zx, fW[7] + lay*DIN, bW[7] + lay*DIN, u2);
        {
            dim3 grid(DM/64, MTOT/128);
            k_gemm2<128,64,16,8,4,true,true><<<grid, 256>>>(
                u2, fW[8] + (size_t)lay*DIN*DM, bW[8] + (size_t)lay*DIN*DM,
                hf, hb, DM, DIN);
        }
    }

    k_final<<<BB*TBWD, 128>>>(hf, hb, patch_out_w, patch_out_b, (float*)d_out);
    (void)in_sizes; (void)n_in; (void)out_size;
}

// round 6
// speedup vs baseline: 1.9292x; 1.2319x over previous
#include <cuda_runtime.h>
#include <cuda_bf16.h>
#include <math.h>
#include <stdint.h>

// ---------------- problem constants ----------------
#define BB 8
#define TPRE 6144
#define CIN 8
#define OUTLEN 2048
#define OUTC 8
#define AUXD 16
#define DM 256
#define DSTATE 32
#define HD 64
#define DIN 512
#define NH 8
#define CONVDIM 576
#define DPROJ 1096
#define NPADI 1152
#define PATCHN 16
#define NTOK 512
#define NMASK 384
#define TFWD 512
#define TBWD 128
#define MFWD (BB*TFWD)    // 4096
#define MBWD (BB*TBWD)    // 1024
#define MTOT (MFWD+MBWD)  // 5120
#define MPATCH (BB*NMASK) // 3072
#define KPATCH 4096
#define KSPLIT 4

// ---------------- scratch ----------------
__device__ __align__(256) float g_aux[BB*DM];
__device__ __align__(256) float g_pp[(size_t)KSPLIT*MPATCH*DM];
__device__ __align__(256) float g_hf[(size_t)BB*NTOK*DM];
__device__ __align__(256) float g_hb[(size_t)BB*TBWD*DM];
__device__ __align__(256) float g_zx[(size_t)MTOT*DPROJ];
__device__ __align__(256) float g_x [(size_t)MTOT*DIN];
__device__ __align__(256) float g_Bb[(size_t)MTOT*DSTATE];
__device__ __align__(256) float g_Cb[(size_t)MTOT*DSTATE];
__device__ __align__(256) float g_dt[(size_t)MTOT*NH];
__device__ __align__(256) float g_y [(size_t)MTOT*DIN];

__device__ __align__(256) __nv_bfloat16 g_pch[(size_t)MPATCH*KPATCH];
__device__ __align__(256) __nv_bfloat16 g_pcl[(size_t)MPATCH*KPATCH];
__device__ __align__(256) __nv_bfloat16 g_uh[(size_t)MTOT*DM];
__device__ __align__(256) __nv_bfloat16 g_ul[(size_t)MTOT*DM];
__device__ __align__(256) __nv_bfloat16 g_u2h[(size_t)MTOT*DIN];
__device__ __align__(256) __nv_bfloat16 g_u2l[(size_t)MTOT*DIN];
__device__ __align__(256) __nv_bfloat16 g_wph[(size_t)DM*KPATCH];
__device__ __align__(256) __nv_bfloat16 g_wpl[(size_t)DM*KPATCH];
__device__ __align__(256) __nv_bfloat16 g_wih[(size_t)4*NPADI*DM];
__device__ __align__(256) __nv_bfloat16 g_wil[(size_t)4*NPADI*DM];
__device__ __align__(256) __nv_bfloat16 g_woh[(size_t)4*DM*DIN];
__device__ __align__(256) __nv_bfloat16 g_wol[(size_t)4*DM*DIN];

__device__ __forceinline__ float silu_f(float v) { return v / (1.0f + expf(-v)); }
__device__ __forceinline__ float softplus_f(float v) { return (v > 20.0f) ? v : log1pf(expf(v)); }

__device__ __forceinline__ void split_bf16(float a, __nv_bfloat16* h, __nv_bfloat16* l) {
    __nv_bfloat16 hh = __float2bfloat16_rn(a);
    *h = hh;
    *l = __float2bfloat16_rn(a - __bfloat162float(hh));
}

// ---------------- baseline-PTX helpers (no arch-specific features) ----------------
__device__ __forceinline__ uint32_t smem_u32(const void* p) {
    uint32_t a;
    asm("{ .reg .u64 t; cvta.to.shared.u64 t, %1; cvt.u32.u64 %0, t; }" : "=r"(a) : "l"(p));
    return a;
}
__device__ __forceinline__ void cp_async16(uint32_t dst, const void* src) {
    asm volatile("cp.async.cg.shared.global [%0], [%1], 16;" :: "r"(dst), "l"(src));
}
#define CP_COMMIT() asm volatile("cp.async.commit_group;" ::: "memory")
#define CP_WAIT0()  asm volatile("cp.async.wait_group 0;" ::: "memory")

__device__ __forceinline__ void ldsm_x4(uint32_t* r, uint32_t addr) {
    asm volatile("ldmatrix.sync.aligned.m8n8.x4.shared.b16 {%0,%1,%2,%3}, [%4];"
                 : "=r"(r[0]), "=r"(r[1]), "=r"(r[2]), "=r"(r[3]) : "r"(addr));
}
__device__ __forceinline__ void mma_bf16(float* d, const uint32_t* a, uint32_t b0, uint32_t b1) {
    asm volatile("mma.sync.aligned.m16n8k16.row.col.f32.bf16.bf16.f32 "
        "{%0,%1,%2,%3}, {%4,%5,%6,%7}, {%8,%9}, {%0,%1,%2,%3};"
        : "+f"(d[0]), "+f"(d[1]), "+f"(d[2]), "+f"(d[3])
        : "r"(a[0]), "r"(a[1]), "r"(a[2]), "r"(a[3]), "r"(b0), "r"(b1));
}

// ---------------- aux bias ----------------
__global__ void k_aux(const float* __restrict__ y_aux, const float* __restrict__ aux_w,
                      const float* __restrict__ aux_b, float* __restrict__ out) {
    __shared__ float ys[BB*AUXD];
    int c = threadIdx.x;
    if (c < BB*AUXD) ys[c] = y_aux[c];
    __syncthreads();
    float wcol[AUXD];
#pragma unroll
    for (int i = 0; i < AUXD; i++) wcol[i] = aux_w[i*DM + c];
    float bias = aux_b[c];
    for (int b = 0; b < BB; b++) {
        float acc = bias;
#pragma unroll
        for (int i = 0; i < AUXD; i++) acc += ys[b*AUXD + i] * wcol[i];
        out[b*DM + c] = silu_f(acc);
    }
}

// ---------------- pre-conv -> bf16 hi/lo ----------------
__global__ void k_preconv(const float* __restrict__ xp, const float* __restrict__ w,
                          const float* __restrict__ bias,
                          __nv_bfloat16* __restrict__ ph, __nv_bfloat16* __restrict__ pl) {
    int m = blockIdx.x;
    int b = m / NMASK, j = m % NMASK;
    int t0 = j * PATCHN;
    __shared__ float xs[20][CIN];
    int tid = threadIdx.x;
    if (tid < 20*CIN) {
        int tt = t0 - 2 + tid / CIN;
        int i = tid % CIN;
        xs[tid/CIN][i] = (tt >= 0 && tt < TPRE) ? xp[((size_t)b*TPRE + tt)*CIN + i] : 0.0f;
    }
    __syncthreads();
    int c = tid;
    float wr[CIN*5];
#pragma unroll
    for (int q = 0; q < CIN*5; q++) wr[q] = w[c*CIN*5 + q];
    float bi = bias[c];
    size_t ob = (size_t)m*KPATCH + c*PATCHN;
#pragma unroll
    for (int k = 0; k < PATCHN; k++) {
        float acc = bi;
#pragma unroll
        for (int i = 0; i < CIN; i++)
#pragma unroll
            for (int q = 0; q < 5; q++)
                acc += xs[k+q][i] * wr[i*5 + q];
        float v = silu_f(acc);
        __nv_bfloat16 h, l; split_bf16(v, &h, &l);
        ph[ob + k] = h; pl[ob + k] = l;
    }
}

// ---------------- weight conversions ----------------
__global__ void k_cvt_patchw(const float* __restrict__ w,
                             __nv_bfloat16* __restrict__ hi, __nv_bfloat16* __restrict__ lo) {
    int i = blockIdx.x * 256 + threadIdx.x;
    float a = w[i];
    __nv_bfloat16 h, l; split_bf16(a, &h, &l);
    hi[i] = h; lo[i] = l;
}

// transpose+convert: src [K,N] -> dst[slot][Npad,K]; slot = blockIdx.z (dir*2+lay)
__global__ void k_cvt_wT(const float* __restrict__ wf, const float* __restrict__ wb,
                         __nv_bfloat16* __restrict__ hi, __nv_bfloat16* __restrict__ lo,
                         int K, int N, int Npad) {
    int slot = blockIdx.z;
    const float* src = ((slot >> 1) ? wb : wf) + (size_t)(slot & 1)*K*N;
    int i = blockIdx.x * 256 + threadIdx.x;
    if (i >= Npad*K) return;
    int n = i / K, k = i % K;
    float a = (n < N) ? src[(size_t)k*N + n] : 0.0f;
    __nv_bfloat16 h, l; split_bf16(a, &h, &l);
    size_t o = (size_t)slot*Npad*K + i;
    hi[o] = h; lo[o] = l;
}

// ---------------- warp-MMA split-bf16 GEMM ----------------
// C = A @ B^T with A[M,K] (hi/lo), B[N,K] (hi/lo). BM=128, BN=64, BK=32.
// 8 warps (4m x 2n), warp tile 32x32. 3 passes: AhBh + AhBl + AlBh.
// MODE 0: patch split-K partials  MODE 1: store zx (guard Nact)  MODE 2: residual +=, split hf/hb
#define PADB 80          // padded row stride in BYTES (40 bf16)
#define OFF_AL 10240
#define OFF_BH 20480
#define OFF_BL 25600
#define BUF_SZ 30720

template<int MODE>
__global__ void __launch_bounds__(256, 2)
k_mmagemm(const __nv_bfloat16* __restrict__ Ah, const __nv_bfloat16* __restrict__ Al,
          const __nv_bfloat16* __restrict__ Bh, const __nv_bfloat16* __restrict__ Bl,
          const __nv_bfloat16* __restrict__ B2h, const __nv_bfloat16* __restrict__ B2l,
          float* __restrict__ Cf, float* __restrict__ Cb,
          int Kchunk, int Kfull, int Nact, int Nstride) {
    extern __shared__ char smem[];
    uint32_t sbase = smem_u32(smem);
    int tid = threadIdx.x;
    int wid = tid >> 5, lane = tid & 31;
    int wm = wid >> 1, wn = wid & 1;
    int m0 = blockIdx.y * 128, n0 = blockIdx.x * 64;
    int kbase = blockIdx.z * Kchunk;
    int NC = Kchunk >> 5;

    const __nv_bfloat16* bh = (MODE != 0 && m0 >= MFWD) ? B2h : Bh;
    const __nv_bfloat16* bl = (MODE != 0 && m0 >= MFWD) ? B2l : Bl;

    float acc[2][4][4];
#pragma unroll
    for (int i = 0; i < 2; i++)
#pragma unroll
        for (int j = 0; j < 4; j++)
#pragma unroll
            for (int q = 0; q < 4; q++) acc[i][j][q] = 0.0f;

    // async copy of chunk c into buffer c&1
    auto issue = [&](int c) {
        int kb = kbase + c*32;
        uint32_t sb = sbase + (c & 1)*BUF_SZ;
#pragma unroll
        for (int it = 0; it < 2; it++) {
            int seg = it*256 + tid;
            int row = seg >> 2, c16 = seg & 3;
            uint32_t d = sb + row*PADB + c16*16;
            const __nv_bfloat16* sA = Ah + (size_t)(m0 + row)*Kfull + kb + c16*8;
            const __nv_bfloat16* sAl = Al + (size_t)(m0 + row)*Kfull + kb + c16*8;
            cp_async16(d, sA);
            cp_async16(d + OFF_AL, sAl);
        }
        {
            int row = tid >> 2, c16 = tid & 3;
            uint32_t d = sb + OFF_BH + row*PADB + c16*16;
            cp_async16(d, bh + (size_t)(n0 + row)*Kfull + kb + c16*8);
            cp_async16(d + (OFF_BL - OFF_BH), bl + (size_t)(n0 + row)*Kfull + kb + c16*8);
        }
        CP_COMMIT();
    };

    issue(0);
    int lrow = lane & 15;
    int lcol16 = (lane >> 4) * 16;  // byte offset within k16 block

    for (int c = 0; c < NC; c++) {
        CP_WAIT0();
        __syncthreads();
        if (c + 1 < NC) issue(c + 1);
        uint32_t sb = sbase + (c & 1)*BUF_SZ;
#pragma unroll
        for (int ks = 0; ks < 2; ks++) {
            uint32_t ah[2][4], al[2][4], bhf[2][4], blf[2][4];
#pragma unroll
            for (int tm = 0; tm < 2; tm++) {
                uint32_t aaddr = sb + (wm*32 + tm*16 + lrow)*PADB + ks*32 + lcol16;
                ldsm_x4(ah[tm], aaddr);
                ldsm_x4(al[tm], aaddr + OFF_AL);
            }
#pragma unroll
            for (int tn = 0; tn < 2; tn++) {
                uint32_t baddr = sb + OFF_BH + (wn*32 + tn*16 + lrow)*PADB + ks*32 + lcol16;
                ldsm_x4(bhf[tn], baddr);
                ldsm_x4(blf[tn], baddr + (OFF_BL - OFF_BH));
            }
#pragma unroll
            for (int tm = 0; tm < 2; tm++)
#pragma unroll
                for (int tn = 0; tn < 2; tn++)
#pragma unroll
                    for (int h = 0; h < 2; h++) {
                        int j = tn*2 + h;
                        mma_bf16(acc[tm][j], ah[tm], bhf[tn][h], bhf[tn][h+2]);
                        mma_bf16(acc[tm][j], ah[tm], blf[tn][h], blf[tn][h+2]);
                        mma_bf16(acc[tm][j], al[tm], bhf[tn][h], bhf[tn][h+2]);
                    }
        }
    }

    // epilogue: lane l holds (row = base+l/4 [+8], cols = n8base + (l%4)*2, +1)
    int lr = lane >> 2;
    int lc2 = (lane & 3) * 2;
#pragma unroll
    for (int tm = 0; tm < 2; tm++) {
        int row0 = m0 + wm*32 + tm*16 + lr;
#pragma unroll
        for (int j = 0; j < 4; j++) {
            int n = n0 + wn*32 + j*8 + lc2;
            if (MODE == 0) {
                float* Cp = Cf + (size_t)blockIdx.z * MPATCH * DM;
                *reinterpret_cast<float2*>(Cp + (size_t)row0*DM + n) =
                    make_float2(acc[tm][j][0], acc[tm][j][1]);
                *reinterpret_cast<float2*>(Cp + (size_t)(row0+8)*DM + n) =
                    make_float2(acc[tm][j][2], acc[tm][j][3]);
            } else if (MODE == 1) {
                if (n < Nact) {
                    *reinterpret_cast<float2*>(Cf + (size_t)row0*Nstride + n) =
                        make_float2(acc[tm][j][0], acc[tm][j][1]);
                    *reinterpret_cast<float2*>(Cf + (size_t)(row0+8)*Nstride + n) =
                        make_float2(acc[tm][j][2], acc[tm][j][3]);
                }
            } else {
#pragma unroll
                for (int half = 0; half < 2; half++) {
                    int m = row0 + half*8;
                    float* p = (m < MFWD) ? (Cf + (size_t)m*DM + n)
                                          : (Cb + (size_t)(m - MFWD)*DM + n);
                    float2 r = *reinterpret_cast<float2*>(p);
                    r.x += acc[tm][j][half*2 + 0];
                    r.y += acc[tm][j][half*2 + 1];
                    *reinterpret_cast<float2*>(p) = r;
                }
            }
        }
    }
}

// reduce patch split-K partials + bias + aux -> hf
__global__ void k_patchreduce(const float* __restrict__ pp, const float* __restrict__ bias,
                              const float* __restrict__ aux, float* __restrict__ hf) {
    int idx = blockIdx.x * blockDim.x + threadIdx.x; // over 3072*256
    int m = idx >> 8, n = idx & 255;
    float v = bias[n];
#pragma unroll
    for (int z = 0; z < KSPLIT; z++) v += pp[(size_t)z*MPATCH*DM + idx];
    int b = m / NMASK, j = m % NMASK;
    hf[((size_t)b*NTOK + j)*DM + n] = v + aux[b*DM + n];
}

// ---------------- mask fill ----------------
__global__ void k_maskfill(const float* __restrict__ mask_token, const float* __restrict__ aux,
                           float* __restrict__ hf, float* __restrict__ hb) {
    int idx = blockIdx.x * blockDim.x + threadIdx.x;
    if (idx >= BB*TBWD*DM) return;
    int c = idx % DM;
    int j = (idx / DM) % TBWD;
    int b = idx / (DM*TBWD);
    float v = mask_token[c] + aux[b*DM + c];
    hf[((size_t)b*NTOK + NMASK + j)*DM + c] = v;
    hb[((size_t)b*TBWD + j)*DM + c] = v;
}

// ---------------- combined rmsnorm -> bf16 hi/lo ----------------
__global__ void k_rmsnorm2(const float* __restrict__ hf, const float* __restrict__ hb,
                           const float* __restrict__ wf, const float* __restrict__ wb,
                           __nv_bfloat16* __restrict__ uh, __nv_bfloat16* __restrict__ ul) {
    int m = blockIdx.x;
    int c = threadIdx.x; // 256
    const float* in = (m < MFWD) ? (hf + (size_t)m*DM) : (hb + (size_t)(m-MFWD)*DM);
    const float* w  = (m < MFWD) ? wf : wb;
    float v = in[c];
    float s = v*v;
#pragma unroll
    for (int o = 16; o > 0; o >>= 1) s += __shfl_xor_sync(0xffffffffu, s, o);
    __shared__ float ws[8];
    if ((c & 31) == 0) ws[c >> 5] = s;
    __syncthreads();
    float tot = 0.0f;
#pragma unroll
    for (int i = 0; i < 8; i++) tot += ws[i];
    float rs = rsqrtf(tot / (float)DM + 1e-5f);
    float o = v * rs * w[c];
    __nv_bfloat16 h, l; split_bf16(o, &h, &l);
    uh[(size_t)m*DM + c] = h; ul[(size_t)m*DM + c] = l;
}

// ---------------- combined conv + dt ----------------
__global__ void k_convdt2(const float* __restrict__ zx,
                          const float* __restrict__ cwf, const float* __restrict__ cbf,
                          const float* __restrict__ dtbf,
                          const float* __restrict__ cwb, const float* __restrict__ cbb,
                          const float* __restrict__ dtbb,
                          float* __restrict__ X, float* __restrict__ Bo, float* __restrict__ Co,
                          float* __restrict__ dto) {
    int m = blockIdx.x;
    int c = threadIdx.x; // 576
    int t;
    const float *cw, *cb, *dtb;
    if (m < MFWD) { t = m & (TFWD-1); cw = cwf; cb = cbf; dtb = dtbf; }
    else          { t = (m - MFWD) & (TBWD-1); cw = cwb; cb = cbb; dtb = dtbb; }
    float acc = cb[c];
    const float* w4 = cw + c*4;
#pragma unroll
    for (int q = 0; q < 4; q++) {
        int tt = t - 3 + q;
        if (tt >= 0) acc += zx[((size_t)(m - 3 + q))*DPROJ + DIN + c] * w4[q];
    }
    float v = silu_f(acc);
    if (c < DIN)             X[(size_t)m*DIN + c] = v;
    else if (c < DIN+DSTATE) Bo[m*DSTATE + (c-DIN)] = v;
    else                     Co[m*DSTATE + (c-DIN-DSTATE)] = v;
    if (c < NH) dto[m*NH + c] = softplus_f(zx[(size_t)m*DPROJ + 2*DIN + 2*DSTATE + c] + dtb[c]);
}

// ---------------- combined scan ----------------
__global__ void __launch_bounds__(1024, 1)
k_scan2(const float* __restrict__ X, const float* __restrict__ Bb, const float* __restrict__ Cb,
        const float* __restrict__ dtb,
        const float* __restrict__ Alogf, const float* __restrict__ Dpf,
        const float* __restrict__ Alogb, const float* __restrict__ Dpb) {
    float* __restrict__ Y = g_y;
    int blk = blockIdx.x;
    int T, rowbase, h;
    float A, Dh;
    if (blk < 64) {
        int b = blk >> 3; h = blk & 7;
        T = TFWD; rowbase = b * TFWD;
        A = -expf(Alogf[h]); Dh = Dpf[h];
    } else {
        int b = (blk - 64) >> 3; h = blk & 7;
        T = TBWD; rowbase = MFWD + b * TBWD;
        A = -expf(Alogb[h]); Dh = Dpb[h];
    }
    int w = threadIdx.x >> 5, lane = threadIdx.x & 31;
    int p0 = w * 2;
    float h0 = 0.0f, h1 = 0.0f;
    for (int t = 0; t < T; t++) {
        int r = rowbase + t;
        float dt = dtb[r*NH + h];
        float Bn = Bb[r*DSTATE + lane];
        float Cn = Cb[r*DSTATE + lane];
        float x0 = X[(size_t)r*DIN + h*HD + p0];
        float x1 = X[(size_t)r*DIN + h*HD + p0 + 1];
        float dA = expf(dt * A);
        h0 = h0*dA + (dt*x0)*Bn;
        h1 = h1*dA + (dt*x1)*Bn;
        float y0 = h0*Cn, y1 = h1*Cn;
#pragma unroll
        for (int o = 16; o > 0; o >>= 1) {
            y0 += __shfl_xor_sync(0xffffffffu, y0, o);
            y1 += __shfl_xor_sync(0xffffffffu, y1, o);
        }
        if (lane == 0) {
            Y[(size_t)r*DIN + h*HD + p0]     = y0 + Dh*x0;
            Y[(size_t)r*DIN + h*HD + p0 + 1] = y1 + Dh*x1;
        }
    }
}

// ---------------- combined gated rmsnorm -> bf16 hi/lo ----------------
__global__ void k_gatednorm2(const float* __restrict__ Y, const float* __restrict__ zx,
                             const float* __restrict__ gwf, const float* __restrict__ gwb,
                             __nv_bfloat16* __restrict__ uh, __nv_bfloat16* __restrict__ ul) {
    int m = blockIdx.x;
    int c = threadIdx.x; // 512
    const float* gw = (m < MFWD) ? gwf : gwb;
    float z = zx[(size_t)m*DPROJ + c];
    float g = Y[(size_t)m*DIN + c] * silu_f(z);
    float s = g*g;
#pragma unroll
    for (int o = 16; o > 0; o >>= 1) s += __shfl_xor_sync(0xffffffffu, s, o);
    __shared__ float ws[16];
    if ((c & 31) == 0) ws[c >> 5] = s;
    __syncthreads();
    float tot = 0.0f;
#pragma unroll
    for (int i = 0; i < 16; i++) tot += ws[i];
    float rs = rsqrtf(tot / (float)DIN + 1e-5f);
    float o = g * rs * gw[c];
    __nv_bfloat16 h, l; split_bf16(o, &h, &l);
    uh[(size_t)m*DIN + c] = h; ul[(size_t)m*DIN + c] = l;
}

// ---------------- final projection ----------------
__global__ void k_final(const float* __restrict__ hf, const float* __restrict__ hb,
                        const float* __restrict__ W, const float* __restrict__ bias,
                        float* __restrict__ out) {
    int blk = blockIdx.x;
    int b = blk >> 7, jj = blk & 127;
    int j = NMASK + jj;
    __shared__ float row[2*DM];
    int tid = threadIdx.x; // 128
    row[tid]       = hf[((size_t)b*NTOK + j)*DM + tid];
    row[tid + 128] = hf[((size_t)b*NTOK + j)*DM + tid + 128];
    int jb = (NTOK - 1) - j;
    row[256 + tid] = hb[((size_t)b*TBWD + jb)*DM + tid];
    row[384 + tid] = hb[((size_t)b*TBWD + jb)*DM + tid + 128];
    __syncthreads();
    float acc = bias[tid];
#pragma unroll 8
    for (int k = 0; k < 2*DM; k++) acc += row[k] * W[k*128 + tid];
    out[(size_t)b*OUTLEN*OUTC + jj*128 + tid] = acc;
}

// ================= host =================
extern "C" void kernel_launch(void* const* d_in, const int* in_sizes, int n_in,
                              void* d_out, int out_size) {
    float *aux, *pp, *hf, *hb, *zx, *X, *Bbuf, *Cbuf, *dt, *Y;
    __nv_bfloat16 *pch, *pcl, *uh, *ul, *u2h, *u2l, *wph, *wpl, *wih, *wil, *woh, *wol;
    cudaGetSymbolAddress((void**)&aux, g_aux);
    cudaGetSymbolAddress((void**)&pp,  g_pp);
    cudaGetSymbolAddress((void**)&hf,  g_hf);
    cudaGetSymbolAddress((void**)&hb,  g_hb);
    cudaGetSymbolAddress((void**)&zx,  g_zx);
    cudaGetSymbolAddress((void**)&X,   g_x);
    cudaGetSymbolAddress((void**)&Bbuf, g_Bb);
    cudaGetSymbolAddress((void**)&Cbuf, g_Cb);
    cudaGetSymbolAddress((void**)&dt,  g_dt);
    cudaGetSymbolAddress((void**)&Y,   g_y);
    cudaGetSymbolAddress((void**)&pch, g_pch);
    cudaGetSymbolAddress((void**)&pcl, g_pcl);
    cudaGetSymbolAddress((void**)&uh,  g_uh);
    cudaGetSymbolAddress((void**)&ul,  g_ul);
    cudaGetSymbolAddress((void**)&u2h, g_u2h);
    cudaGetSymbolAddress((void**)&u2l, g_u2l);
    cudaGetSymbolAddress((void**)&wph, g_wph);
    cudaGetSymbolAddress((void**)&wpl, g_wpl);
    cudaGetSymbolAddress((void**)&wih, g_wih);
    cudaGetSymbolAddress((void**)&wil, g_wil);
    cudaGetSymbolAddress((void**)&woh, g_woh);
    cudaGetSymbolAddress((void**)&wol, g_wol);

    const float* x_prefix   = (const float*)d_in[0];
    const float* y_aux      = (const float*)d_in[1];
    const float* pre_conv_w = (const float*)d_in[2];
    const float* pre_conv_b = (const float*)d_in[3];
    const float* patch_w    = (const float*)d_in[4];
    const float* patch_b    = (const float*)d_in[5];
    const float* mask_token = (const float*)d_in[6];
    const float* aux_w      = (const float*)d_in[7];
    const float* aux_b      = (const float*)d_in[8];

    const float *patch_out_w, *patch_out_b;
    int fbase, bbase;
    if (n_in > 9 && in_sizes[9] == 65536) {
        patch_out_w = (const float*)d_in[9];
        patch_out_b = (const float*)d_in[10];
        fbase = 11; bbase = 20;
    } else {
        fbase = 9; bbase = 18;
        patch_out_w = (const float*)d_in[27];
        patch_out_b = (const float*)d_in[28];
    }
    const float* fW[9]; const float* bW[9];
    for (int i = 0; i < 9; i++) { fW[i] = (const float*)d_in[fbase+i]; bW[i] = (const float*)d_in[bbase+i]; }

    cudaFuncSetAttribute(k_mmagemm<0>, cudaFuncAttributeMaxDynamicSharedMemorySize, 2*BUF_SZ);
    cudaFuncSetAttribute(k_mmagemm<1>, cudaFuncAttributeMaxDynamicSharedMemorySize, 2*BUF_SZ);
    cudaFuncSetAttribute(k_mmagemm<2>, cudaFuncAttributeMaxDynamicSharedMemorySize, 2*BUF_SZ);

    // stage 0: aux, preconv (bf16), weight conversions
    k_aux<<<1, 256>>>(y_aux, aux_w, aux_b, aux);
    k_preconv<<<MPATCH, 256>>>(x_prefix, pre_conv_w, pre_conv_b, pch, pcl);
    k_cvt_patchw<<<(DM*KPATCH)/256, 256>>>(patch_w, wph, wpl);
    k_cvt_wT<<<dim3((NPADI*DM)/256, 1, 4), 256>>>(fW[1], bW[1], wih, wil, DM, DPROJ, NPADI);
    k_cvt_wT<<<dim3((DM*DIN)/256, 1, 4), 256>>>(fW[8], bW[8], woh, wol, DIN, DM, DM);

    // patch GEMM: [3072 x 256] split-K=4 partials, then reduce(+bias+aux) -> hf
    k_mmagemm<0><<<dim3(DM/64, MPATCH/128, KSPLIT), 256, 2*BUF_SZ>>>(
        pch, pcl, wph, wpl, wph, wpl, pp, nullptr, KPATCH/KSPLIT, KPATCH, DM, DM);
    k_patchreduce<<<(MPATCH*DM)/256, 256>>>(pp, patch_b, aux, hf);
    k_maskfill<<<(BB*TBWD*DM + 255)/256, 256>>>(mask_token, aux, hf, hb);

    for (int lay = 0; lay < 2; lay++) {
        k_rmsnorm2<<<MTOT, DM>>>(hf, hb, fW[0] + lay*DM, bW[0] + lay*DM, uh, ul);
        // inproj: [5120 x 1152pad], K=256
        k_mmagemm<1><<<dim3(NPADI/64, MTOT/128, 1), 256, 2*BUF_SZ>>>(
            uh, ul,
            wih + (size_t)lay*NPADI*DM,     wil + (size_t)lay*NPADI*DM,
            wih + (size_t)(2+lay)*NPADI*DM, wil + (size_t)(2+lay)*NPADI*DM,
            zx, nullptr, DM, DM, DPROJ, DPROJ);
        k_convdt2<<<MTOT, CONVDIM>>>(zx,
            fW[2] + lay*CONVDIM*4, fW[3] + lay*CONVDIM, fW[4] + lay*NH,
            bW[2] + lay*CONVDIM*4, bW[3] + lay*CONVDIM, bW[4] + lay*NH,
            X, Bbuf, Cbuf, dt);
        k_scan2<<<128, 1024>>>(X, Bbuf, Cbuf, dt,
            fW[5] + lay*NH, fW[6] + lay*NH, bW[5] + lay*NH, bW[6] + lay*NH);
        k_gatednorm2<<<MTOT, DIN>>>(Y, zx, fW[7] + lay*DIN, bW[7] + lay*DIN, u2h, u2l);
        // outproj: [5120 x 256], K=512, residual accumulate, split hf/hb
        k_mmagemm<2><<<dim3(DM/64, MTOT/128, 1), 256, 2*BUF_SZ>>>(
            u2h, u2l,
            woh + (size_t)lay*DM*DIN,     wol + (size_t)lay*DM*DIN,
            woh + (size_t)(2+lay)*DM*DIN, wol + (size_t)(2+lay)*DM*DIN,
            hf, hb, DIN, DIN, DM, DM);
    }

    k_final<<<BB*TBWD, 128>>>(hf, hb, patch_out_w, patch_out_b, (float*)d_out);
    (void)in_sizes; (void)n_in; (void)out_size;
}

// round 7
// speedup vs baseline: 2.0183x; 1.0462x over previous
#include <cuda_runtime.h>
#include <cuda_bf16.h>
#include <math.h>
#include <stdint.h>

// ---------------- problem constants ----------------
#define BB 8
#define TPRE 6144
#define CIN 8
#define OUTLEN 2048
#define OUTC 8
#define AUXD 16
#define DM 256
#define DSTATE 32
#define HD 64
#define DIN 512
#define NH 8
#define CONVDIM 576
#define DPROJ 1096
#define NPADI 1152
#define PATCHN 16
#define NTOK 512
#define NMASK 384
#define TFWD 512
#define TBWD 128
#define MFWD (BB*TFWD)    // 4096
#define MBWD (BB*TBWD)    // 1024
#define MTOT (MFWD+MBWD)  // 5120
#define MPATCH (BB*NMASK) // 3072
#define KPATCH 4096
#define KSPLIT 4

// ---------------- scratch ----------------
__device__ __align__(256) float g_aux[BB*DM];
__device__ __align__(256) float g_pp[(size_t)KSPLIT*MPATCH*DM];
__device__ __align__(256) float g_hf[(size_t)BB*NTOK*DM];
__device__ __align__(256) float g_hb[(size_t)BB*TBWD*DM];
__device__ __align__(256) float g_zx[(size_t)MTOT*DPROJ];
__device__ __align__(256) float g_x [(size_t)MTOT*DIN];
__device__ __align__(256) float g_Bb[(size_t)MTOT*DSTATE];
__device__ __align__(256) float g_Cb[(size_t)MTOT*DSTATE];
__device__ __align__(256) float g_dt[(size_t)MTOT*NH];
__device__ __align__(256) float g_y [(size_t)MTOT*DIN];

__device__ __align__(256) __nv_bfloat16 g_pch[(size_t)MPATCH*KPATCH];
__device__ __align__(256) __nv_bfloat16 g_pcl[(size_t)MPATCH*KPATCH];
__device__ __align__(256) __nv_bfloat16 g_uh[(size_t)MTOT*DM];
__device__ __align__(256) __nv_bfloat16 g_ul[(size_t)MTOT*DM];
__device__ __align__(256) __nv_bfloat16 g_u2h[(size_t)MTOT*DIN];
__device__ __align__(256) __nv_bfloat16 g_u2l[(size_t)MTOT*DIN];
__device__ __align__(256) __nv_bfloat16 g_wph[(size_t)DM*KPATCH];
__device__ __align__(256) __nv_bfloat16 g_wpl[(size_t)DM*KPATCH];
__device__ __align__(256) __nv_bfloat16 g_wih[(size_t)4*NPADI*DM];
__device__ __align__(256) __nv_bfloat16 g_wil[(size_t)4*NPADI*DM];
__device__ __align__(256) __nv_bfloat16 g_woh[(size_t)4*DM*DIN];
__device__ __align__(256) __nv_bfloat16 g_wol[(size_t)4*DM*DIN];

__device__ __forceinline__ float silu_f(float v) { return v / (1.0f + expf(-v)); }
__device__ __forceinline__ float softplus_f(float v) { return (v > 20.0f) ? v : log1pf(expf(v)); }

__device__ __forceinline__ void split_bf16(float a, __nv_bfloat16* h, __nv_bfloat16* l) {
    __nv_bfloat16 hh = __float2bfloat16_rn(a);
    *h = hh;
    *l = __float2bfloat16_rn(a - __bfloat162float(hh));
}

// ---------------- baseline-PTX helpers ----------------
__device__ __forceinline__ uint32_t smem_u32(const void* p) {
    uint32_t a;
    asm("{ .reg .u64 t; cvta.to.shared.u64 t, %1; cvt.u32.u64 %0, t; }" : "=r"(a) : "l"(p));
    return a;
}
__device__ __forceinline__ void cp_async16(uint32_t dst, const void* src) {
    asm volatile("cp.async.cg.shared.global [%0], [%1], 16;" :: "r"(dst), "l"(src));
}
#define CP_COMMIT() asm volatile("cp.async.commit_group;" ::: "memory")
#define CP_WAIT0()  asm volatile("cp.async.wait_group 0;" ::: "memory")

__device__ __forceinline__ void ldsm_x4(uint32_t* r, uint32_t addr) {
    asm volatile("ldmatrix.sync.aligned.m8n8.x4.shared.b16 {%0,%1,%2,%3}, [%4];"
                 : "=r"(r[0]), "=r"(r[1]), "=r"(r[2]), "=r"(r[3]) : "r"(addr));
}
__device__ __forceinline__ void mma_bf16(float* d, const uint32_t* a, uint32_t b0, uint32_t b1) {
    asm volatile("mma.sync.aligned.m16n8k16.row.col.f32.bf16.bf16.f32 "
        "{%0,%1,%2,%3}, {%4,%5,%6,%7}, {%8,%9}, {%0,%1,%2,%3};"
        : "+f"(d[0]), "+f"(d[1]), "+f"(d[2]), "+f"(d[3])
        : "r"(a[0]), "r"(a[1]), "r"(a[2]), "r"(a[3]), "r"(b0), "r"(b1));
}

#define PADB 80  // padded SMEM row stride in bytes (32 k-bf16 = 64B + 16 pad)

// ---------------- aux bias ----------------
__global__ void k_aux(const float* __restrict__ y_aux, const float* __restrict__ aux_w,
                      const float* __restrict__ aux_b, float* __restrict__ out) {
    __shared__ float ys[BB*AUXD];
    int c = threadIdx.x;
    if (c < BB*AUXD) ys[c] = y_aux[c];
    __syncthreads();
    float wcol[AUXD];
#pragma unroll
    for (int i = 0; i < AUXD; i++) wcol[i] = aux_w[i*DM + c];
    float bias = aux_b[c];
    for (int b = 0; b < BB; b++) {
        float acc = bias;
#pragma unroll
        for (int i = 0; i < AUXD; i++) acc += ys[b*AUXD + i] * wcol[i];
        out[b*DM + c] = silu_f(acc);
    }
}

// ---------------- pre-conv -> bf16 hi/lo ----------------
__global__ void k_preconv(const float* __restrict__ xp, const float* __restrict__ w,
                          const float* __restrict__ bias,
                          __nv_bfloat16* __restrict__ ph, __nv_bfloat16* __restrict__ pl) {
    int m = blockIdx.x;
    int b = m / NMASK, j = m % NMASK;
    int t0 = j * PATCHN;
    __shared__ float xs[20][CIN];
    int tid = threadIdx.x;
    if (tid < 20*CIN) {
        int tt = t0 - 2 + tid / CIN;
        int i = tid % CIN;
        xs[tid/CIN][i] = (tt >= 0 && tt < TPRE) ? xp[((size_t)b*TPRE + tt)*CIN + i] : 0.0f;
    }
    __syncthreads();
    int c = tid;
    float wr[CIN*5];
#pragma unroll
    for (int q = 0; q < CIN*5; q++) wr[q] = w[c*CIN*5 + q];
    float bi = bias[c];
    size_t ob = (size_t)m*KPATCH + c*PATCHN;
#pragma unroll
    for (int k = 0; k < PATCHN; k++) {
        float acc = bi;
#pragma unroll
        for (int i = 0; i < CIN; i++)
#pragma unroll
            for (int q = 0; q < 5; q++)
                acc += xs[k+q][i] * wr[i*5 + q];
        float v = silu_f(acc);
        __nv_bfloat16 h, l; split_bf16(v, &h, &l);
        ph[ob + k] = h; pl[ob + k] = l;
    }
}

// ---------------- weight conversions ----------------
__global__ void k_cvt_patchw(const float* __restrict__ w,
                             __nv_bfloat16* __restrict__ hi, __nv_bfloat16* __restrict__ lo) {
    int i = blockIdx.x * 256 + threadIdx.x;
    float a = w[i];
    __nv_bfloat16 h, l; split_bf16(a, &h, &l);
    hi[i] = h; lo[i] = l;
}

__global__ void k_cvt_wT(const float* __restrict__ wf, const float* __restrict__ wb,
                         __nv_bfloat16* __restrict__ hi, __nv_bfloat16* __restrict__ lo,
                         int K, int N, int Npad) {
    int slot = blockIdx.z;
    const float* src = ((slot >> 1) ? wb : wf) + (size_t)(slot & 1)*K*N;
    int i = blockIdx.x * 256 + threadIdx.x;
    if (i >= Npad*K) return;
    int n = i / K, k = i % K;
    float a = (n < N) ? src[(size_t)k*N + n] : 0.0f;
    __nv_bfloat16 h, l; split_bf16(a, &h, &l);
    size_t o = (size_t)slot*Npad*K + i;
    hi[o] = h; lo[o] = l;
}

// ================= GEMM v2: 128x128 tile, 512 threads (16 warps 4m x 4n) =================
// MODE 0: patch split-K partials   MODE 1: inproj store (guard Nact)
#define B2_OFF_AL 10240
#define B2_OFF_BH 20480
#define B2_OFF_BL 30720
#define BUF2_SZ   40960

template<int MODE>
__global__ void __launch_bounds__(512, 1)
k_mmagemm512(const __nv_bfloat16* __restrict__ Ah, const __nv_bfloat16* __restrict__ Al,
             const __nv_bfloat16* __restrict__ Bh, const __nv_bfloat16* __restrict__ Bl,
             const __nv_bfloat16* __restrict__ B2h, const __nv_bfloat16* __restrict__ B2l,
             float* __restrict__ Cf, int Kchunk, int Kfull, int Nact, int Nstride) {
    extern __shared__ char smem[];
    uint32_t sbase = smem_u32(smem);
    int tid = threadIdx.x;
    int wid = tid >> 5, lane = tid & 31;
    int wm = wid >> 2, wn = wid & 3;
    int m0 = blockIdx.y * 128, n0 = blockIdx.x * 128;
    int kbase = blockIdx.z * Kchunk;
    int NC = Kchunk >> 5;

    const __nv_bfloat16* bh = (MODE == 1 && m0 >= MFWD) ? B2h : Bh;
    const __nv_bfloat16* bl = (MODE == 1 && m0 >= MFWD) ? B2l : Bl;

    float acc[2][4][4];
#pragma unroll
    for (int i = 0; i < 2; i++)
#pragma unroll
        for (int j = 0; j < 4; j++)
#pragma unroll
            for (int q = 0; q < 4; q++) acc[i][j][q] = 0.0f;

    int lrow = tid >> 2, lc16 = tid & 3;  // 512 threads: 128 rows x 4 segs
    auto issue = [&](int c) {
        int kb = kbase + c*32;
        uint32_t sb = sbase + (c & 1)*BUF2_SZ;
        uint32_t d = sb + lrow*PADB + lc16*16;
        size_t go = (size_t)lrow*Kfull + kb + lc16*8;
        cp_async16(d,             Ah + (size_t)m0*Kfull + go);
        cp_async16(d + B2_OFF_AL, Al + (size_t)m0*Kfull + go);
        uint32_t db = sb + B2_OFF_BH + lrow*PADB + lc16*16;
        size_t gb = (size_t)lrow*Kfull + kb + lc16*8;
        cp_async16(db,                          bh + (size_t)n0*Kfull + gb);
        cp_async16(db + (B2_OFF_BL - B2_OFF_BH), bl + (size_t)n0*Kfull + gb);
        CP_COMMIT();
    };

    issue(0);
    int mrow = lane & 15;
    int mcol16 = (lane >> 4) * 16;

    for (int c = 0; c < NC; c++) {
        CP_WAIT0();
        __syncthreads();
        if (c + 1 < NC) issue(c + 1);
        uint32_t sb = sbase + (c & 1)*BUF2_SZ;
#pragma unroll
        for (int ks = 0; ks < 2; ks++) {
            uint32_t ah[2][4], al[2][4], bhf[2][4], blf[2][4];
#pragma unroll
            for (int tm = 0; tm < 2; tm++) {
                uint32_t aaddr = sb + (wm*32 + tm*16 + mrow)*PADB + ks*32 + mcol16;
                ldsm_x4(ah[tm], aaddr);
                ldsm_x4(al[tm], aaddr + B2_OFF_AL);
            }
#pragma unroll
            for (int tn = 0; tn < 2; tn++) {
                uint32_t baddr = sb + B2_OFF_BH + (wn*32 + tn*16 + mrow)*PADB + ks*32 + mcol16;
                ldsm_x4(bhf[tn], baddr);
                ldsm_x4(blf[tn], baddr + (B2_OFF_BL - B2_OFF_BH));
            }
#pragma unroll
            for (int tm = 0; tm < 2; tm++)
#pragma unroll
                for (int tn = 0; tn < 2; tn++)
#pragma unroll
                    for (int h = 0; h < 2; h++) {
                        int j = tn*2 + h;
                        mma_bf16(acc[tm][j], ah[tm], bhf[tn][h], bhf[tn][h+2]);
                        mma_bf16(acc[tm][j], ah[tm], blf[tn][h], blf[tn][h+2]);
                        mma_bf16(acc[tm][j], al[tm], bhf[tn][h], bhf[tn][h+2]);
                    }
        }
    }

    int lr = lane >> 2;
    int lc2 = (lane & 3) * 2;
#pragma unroll
    for (int tm = 0; tm < 2; tm++) {
        int row0 = m0 + wm*32 + tm*16 + lr;
#pragma unroll
        for (int j = 0; j < 4; j++) {
            int n = n0 + wn*32 + j*8 + lc2;
            if (MODE == 0) {
                float* Cp = Cf + (size_t)blockIdx.z * MPATCH * DM;
                *reinterpret_cast<float2*>(Cp + (size_t)row0*DM + n) =
                    make_float2(acc[tm][j][0], acc[tm][j][1]);
                *reinterpret_cast<float2*>(Cp + (size_t)(row0+8)*DM + n) =
                    make_float2(acc[tm][j][2], acc[tm][j][3]);
            } else {
                if (n < Nact) {
                    *reinterpret_cast<float2*>(Cf + (size_t)row0*Nstride + n) =
                        make_float2(acc[tm][j][0], acc[tm][j][1]);
                    *reinterpret_cast<float2*>(Cf + (size_t)(row0+8)*Nstride + n) =
                        make_float2(acc[tm][j][2], acc[tm][j][3]);
                }
            }
        }
    }
}

// ================= GEMM v1 (R6, proven): 128x64 tile, 256 threads — outproj residual =================
#define OFF_AL 10240
#define OFF_BH 20480
#define OFF_BL 25600
#define BUF_SZ 30720

__global__ void __launch_bounds__(256, 2)
k_mmagemm64(const __nv_bfloat16* __restrict__ Ah, const __nv_bfloat16* __restrict__ Al,
            const __nv_bfloat16* __restrict__ Bh, const __nv_bfloat16* __restrict__ Bl,
            const __nv_bfloat16* __restrict__ B2h, const __nv_bfloat16* __restrict__ B2l,
            float* __restrict__ Cf, float* __restrict__ Cb, int Kfull) {
    extern __shared__ char smem[];
    uint32_t sbase = smem_u32(smem);
    int tid = threadIdx.x;
    int wid = tid >> 5, lane = tid & 31;
    int wm = wid >> 1, wn = wid & 1;
    int m0 = blockIdx.y * 128, n0 = blockIdx.x * 64;
    int NC = Kfull >> 5;

    const __nv_bfloat16* bh = (m0 >= MFWD) ? B2h : Bh;
    const __nv_bfloat16* bl = (m0 >= MFWD) ? B2l : Bl;

    float acc[2][4][4];
#pragma unroll
    for (int i = 0; i < 2; i++)
#pragma unroll
        for (int j = 0; j < 4; j++)
#pragma unroll
            for (int q = 0; q < 4; q++) acc[i][j][q] = 0.0f;

    auto issue = [&](int c) {
        int kb = c*32;
        uint32_t sb = sbase + (c & 1)*BUF_SZ;
#pragma unroll
        for (int it = 0; it < 2; it++) {
            int seg = it*256 + tid;
            int row = seg >> 2, c16 = seg & 3;
            uint32_t d = sb + row*PADB + c16*16;
            cp_async16(d,          Ah + (size_t)(m0 + row)*Kfull + kb + c16*8);
            cp_async16(d + OFF_AL, Al + (size_t)(m0 + row)*Kfull + kb + c16*8);
        }
        {
            int row = tid >> 2, c16 = tid & 3;
            uint32_t d = sb + OFF_BH + row*PADB + c16*16;
            cp_async16(d, bh + (size_t)(n0 + row)*Kfull + kb + c16*8);
            cp_async16(d + (OFF_BL - OFF_BH), bl + (size_t)(n0 + row)*Kfull + kb + c16*8);
        }
        CP_COMMIT();
    };

    issue(0);
    int lrow = lane & 15;
    int lcol16 = (lane >> 4) * 16;

    for (int c = 0; c < NC; c++) {
        CP_WAIT0();
        __syncthreads();
        if (c + 1 < NC) issue(c + 1);
        uint32_t sb = sbase + (c & 1)*BUF_SZ;
#pragma unroll
        for (int ks = 0; ks < 2; ks++) {
            uint32_t ah[2][4], al[2][4], bhf[2][4], blf[2][4];
#pragma unroll
            for (int tm = 0; tm < 2; tm++) {
                uint32_t aaddr = sb + (wm*32 + tm*16 + lrow)*PADB + ks*32 + lcol16;
                ldsm_x4(ah[tm], aaddr);
                ldsm_x4(al[tm], aaddr + OFF_AL);
            }
#pragma unroll
            for (int tn = 0; tn < 2; tn++) {
                uint32_t baddr = sb + OFF_BH + (wn*32 + tn*16 + lrow)*PADB + ks*32 + lcol16;
                ldsm_x4(bhf[tn], baddr);
                ldsm_x4(blf[tn], baddr + (OFF_BL - OFF_BH));
            }
#pragma unroll
            for (int tm = 0; tm < 2; tm++)
#pragma unroll
                for (int tn = 0; tn < 2; tn++)
#pragma unroll
                    for (int h = 0; h < 2; h++) {
                        int j = tn*2 + h;
                        mma_bf16(acc[tm][j], ah[tm], bhf[tn][h], bhf[tn][h+2]);
                        mma_bf16(acc[tm][j], ah[tm], blf[tn][h], blf[tn][h+2]);
                        mma_bf16(acc[tm][j], al[tm], bhf[tn][h], bhf[tn][h+2]);
                    }
        }
    }

    int lr = lane >> 2;
    int lc2 = (lane & 3) * 2;
#pragma unroll
    for (int tm = 0; tm < 2; tm++) {
        int row0 = m0 + wm*32 + tm*16 + lr;
#pragma unroll
        for (int j = 0; j < 4; j++) {
            int n = n0 + wn*32 + j*8 + lc2;
#pragma unroll
            for (int half = 0; half < 2; half++) {
                int m = row0 + half*8;
                float* p = (m < MFWD) ? (Cf + (size_t)m*DM + n)
                                      : (Cb + (size_t)(m - MFWD)*DM + n);
                float2 r = *reinterpret_cast<float2*>(p);
                r.x += acc[tm][j][half*2 + 0];
                r.y += acc[tm][j][half*2 + 1];
                *reinterpret_cast<float2*>(p) = r;
            }
        }
    }
}

// reduce patch split-K partials + bias + aux -> hf
__global__ void k_patchreduce(const float* __restrict__ pp, const float* __restrict__ bias,
                              const float* __restrict__ aux, float* __restrict__ hf) {
    int idx = blockIdx.x * blockDim.x + threadIdx.x;
    int m = idx >> 8, n = idx & 255;
    float v = bias[n];
#pragma unroll
    for (int z = 0; z < KSPLIT; z++) v += pp[(size_t)z*MPATCH*DM + idx];
    int b = m / NMASK, j = m % NMASK;
    hf[((size_t)b*NTOK + j)*DM + n] = v + aux[b*DM + n];
}

// ---------------- mask fill ----------------
__global__ void k_maskfill(const float* __restrict__ mask_token, const float* __restrict__ aux,
                           float* __restrict__ hf, float* __restrict__ hb) {
    int idx = blockIdx.x * blockDim.x + threadIdx.x;
    if (idx >= BB*TBWD*DM) return;
    int c = idx % DM;
    int j = (idx / DM) % TBWD;
    int b = idx / (DM*TBWD);
    float v = mask_token[c] + aux[b*DM + c];
    hf[((size_t)b*NTOK + NMASK + j)*DM + c] = v;
    hb[((size_t)b*TBWD + j)*DM + c] = v;
}

// ---------------- combined rmsnorm -> bf16 hi/lo ----------------
__global__ void k_rmsnorm2(const float* __restrict__ hf, const float* __restrict__ hb,
                           const float* __restrict__ wf, const float* __restrict__ wb,
                           __nv_bfloat16* __restrict__ uh, __nv_bfloat16* __restrict__ ul) {
    int m = blockIdx.x;
    int c = threadIdx.x; // 256
    const float* in = (m < MFWD) ? (hf + (size_t)m*DM) : (hb + (size_t)(m-MFWD)*DM);
    const float* w  = (m < MFWD) ? wf : wb;
    float v = in[c];
    float s = v*v;
#pragma unroll
    for (int o = 16; o > 0; o >>= 1) s += __shfl_xor_sync(0xffffffffu, s, o);
    __shared__ float ws[8];
    if ((c & 31) == 0) ws[c >> 5] = s;
    __syncthreads();
    float tot = 0.0f;
#pragma unroll
    for (int i = 0; i < 8; i++) tot += ws[i];
    float rs = rsqrtf(tot / (float)DM + 1e-5f);
    float o = v * rs * w[c];
    __nv_bfloat16 h, l; split_bf16(o, &h, &l);
    uh[(size_t)m*DM + c] = h; ul[(size_t)m*DM + c] = l;
}

// ---------------- combined conv + dt ----------------
__global__ void k_convdt2(const float* __restrict__ zx,
                          const float* __restrict__ cwf, const float* __restrict__ cbf,
                          const float* __restrict__ dtbf,
                          const float* __restrict__ cwb, const float* __restrict__ cbb,
                          const float* __restrict__ dtbb,
                          float* __restrict__ X, float* __restrict__ Bo, float* __restrict__ Co,
                          float* __restrict__ dto) {
    int m = blockIdx.x;
    int c = threadIdx.x; // 576
    int t;
    const float *cw, *cb, *dtb;
    if (m < MFWD) { t = m & (TFWD-1); cw = cwf; cb = cbf; dtb = dtbf; }
    else          { t = (m - MFWD) & (TBWD-1); cw = cwb; cb = cbb; dtb = dtbb; }
    float acc = cb[c];
    const float* w4 = cw + c*4;
#pragma unroll
    for (int q = 0; q < 4; q++) {
        int tt = t - 3 + q;
        if (tt >= 0) acc += zx[((size_t)(m - 3 + q))*DPROJ + DIN + c] * w4[q];
    }
    float v = silu_f(acc);
    if (c < DIN)             X[(size_t)m*DIN + c] = v;
    else if (c < DIN+DSTATE) Bo[m*DSTATE + (c-DIN)] = v;
    else                     Co[m*DSTATE + (c-DIN-DSTATE)] = v;
    if (c < NH) dto[m*NH + c] = softplus_f(zx[(size_t)m*DPROJ + 2*DIN + 2*DSTATE + c] + dtb[c]);
}

// ---------------- scan v2 ----------------
// block = one (b,h): 512 threads, 16 warps. Warp owns 4 p's (pg = lane>>3),
// 8-lane group owns 4 n's each (ng = lane&7, n = ng*4..+3). 3-shfl reduction.
__global__ void __launch_bounds__(512, 2)
k_scan3(const float* __restrict__ X, const float* __restrict__ Bb, const float* __restrict__ Cb,
        const float* __restrict__ dtb,
        const float* __restrict__ Alogf, const float* __restrict__ Dpf,
        const float* __restrict__ Alogb, const float* __restrict__ Dpb) {
    float* __restrict__ Y = g_y;
    int blk = blockIdx.x;
    int T, rowbase, h;
    float A, Dh;
    if (blk < 64) {
        int b = blk >> 3; h = blk & 7;
        T = TFWD; rowbase = b * TFWD;
        A = -expf(Alogf[h]); Dh = Dpf[h];
    } else {
        int b = (blk - 64) >> 3; h = blk & 7;
        T = TBWD; rowbase = MFWD + b * TBWD;
        A = -expf(Alogb[h]); Dh = Dpb[h];
    }
    int wid = threadIdx.x >> 5, lane = threadIdx.x & 31;
    int pg = lane >> 3, ng = lane & 7;
    int p = wid*4 + pg;
    const float4* B4 = reinterpret_cast<const float4*>(Bb);
    const float4* C4 = reinterpret_cast<const float4*>(Cb);

    float s0 = 0.f, s1 = 0.f, s2 = 0.f, s3 = 0.f;
    int r = rowbase;
    float dtc = dtb[(size_t)r*NH + h];
    float4 Bv = B4[(size_t)r*8 + ng];
    float4 Cv = C4[(size_t)r*8 + ng];
    float xc = X[(size_t)r*DIN + h*HD + p];

    for (int t = 0; t < T; t++) {
        float dtn, xn; float4 Bn, Cn;
        if (t + 1 < T) {
            int rn = r + 1;
            dtn = dtb[(size_t)rn*NH + h];
            Bn = B4[(size_t)rn*8 + ng];
            Cn = C4[(size_t)rn*8 + ng];
            xn = X[(size_t)rn*DIN + h*HD + p];
        }
        float dA = expf(dtc * A);
        float dx = dtc * xc;
        s0 = s0*dA + dx*Bv.x;
        s1 = s1*dA + dx*Bv.y;
        s2 = s2*dA + dx*Bv.z;
        s3 = s3*dA + dx*Bv.w;
        float y = s0*Cv.x + s1*Cv.y + s2*Cv.z + s3*Cv.w;
        y += __shfl_xor_sync(0xffffffffu, y, 1);
        y += __shfl_xor_sync(0xffffffffu, y, 2);
        y += __shfl_xor_sync(0xffffffffu, y, 4);
        if (ng == 0) Y[(size_t)r*DIN + h*HD + p] = y + Dh*xc;
        if (t + 1 < T) { dtc = dtn; Bv = Bn; Cv = Cn; xc = xn; r++; }
    }
}

// ---------------- combined gated rmsnorm -> bf16 hi/lo ----------------
__global__ void k_gatednorm2(const float* __restrict__ Y, const float* __restrict__ zx,
                             const float* __restrict__ gwf, const float* __restrict__ gwb,
                             __nv_bfloat16* __restrict__ uh, __nv_bfloat16* __restrict__ ul) {
    int m = blockIdx.x;
    int c = threadIdx.x; // 512
    const float* gw = (m < MFWD) ? gwf : gwb;
    float z = zx[(size_t)m*DPROJ + c];
    float g = Y[(size_t)m*DIN + c] * silu_f(z);
    float s = g*g;
#pragma unroll
    for (int o = 16; o > 0; o >>= 1) s += __shfl_xor_sync(0xffffffffu, s, o);
    __shared__ float ws[16];
    if ((c & 31) == 0) ws[c >> 5] = s;
    __syncthreads();
    float tot = 0.0f;
#pragma unroll
    for (int i = 0; i < 16; i++) tot += ws[i];
    float rs = rsqrtf(tot / (float)DIN + 1e-5f);
    float o = g * rs * gw[c];
    __nv_bfloat16 h, l; split_bf16(o, &h, &l);
    uh[(size_t)m*DIN + c] = h; ul[(size_t)m*DIN + c] = l;
}

// ---------------- final projection ----------------
__global__ void k_final(const float* __restrict__ hf, const float* __restrict__ hb,
                        const float* __restrict__ W, const float* __restrict__ bias,
                        float* __restrict__ out) {
    int blk = blockIdx.x;
    int b = blk >> 7, jj = blk & 127;
    int j = NMASK + jj;
    __shared__ float row[2*DM];
    int tid = threadIdx.x; // 128
    row[tid]       = hf[((size_t)b*NTOK + j)*DM + tid];
    row[tid + 128] = hf[((size_t)b*NTOK + j)*DM + tid + 128];
    int jb = (NTOK - 1) - j;
    row[256 + tid] = hb[((size_t)b*TBWD + jb)*DM + tid];
    row[384 + tid] = hb[((size_t)b*TBWD + jb)*DM + tid + 128];
    __syncthreads();
    float acc = bias[tid];
#pragma unroll 8
    for (int k = 0; k < 2*DM; k++) acc += row[k] * W[k*128 + tid];
    out[(size_t)b*OUTLEN*OUTC + jj*128 + tid] = acc;
}

// ================= host =================
extern "C" void kernel_launch(void* const* d_in, const int* in_sizes, int n_in,
                              void* d_out, int out_size) {
    float *aux, *pp, *hf, *hb, *zx, *X, *Bbuf, *Cbuf, *dt, *Y;
    __nv_bfloat16 *pch, *pcl, *uh, *ul, *u2h, *u2l, *wph, *wpl, *wih, *wil, *woh, *wol;
    cudaGetSymbolAddress((void**)&aux, g_aux);
    cudaGetSymbolAddress((void**)&pp,  g_pp);
    cudaGetSymbolAddress((void**)&hf,  g_hf);
    cudaGetSymbolAddress((void**)&hb,  g_hb);
    cudaGetSymbolAddress((void**)&zx,  g_zx);
    cudaGetSymbolAddress((void**)&X,   g_x);
    cudaGetSymbolAddress((void**)&Bbuf, g_Bb);
    cudaGetSymbolAddress((void**)&Cbuf, g_Cb);
    cudaGetSymbolAddress((void**)&dt,  g_dt);
    cudaGetSymbolAddress((void**)&Y,   g_y);
    cudaGetSymbolAddress((void**)&pch, g_pch);
    cudaGetSymbolAddress((void**)&pcl, g_pcl);
    cudaGetSymbolAddress((void**)&uh,  g_uh);
    cudaGetSymbolAddress((void**)&ul,  g_ul);
    cudaGetSymbolAddress((void**)&u2h, g_u2h);
    cudaGetSymbolAddress((void**)&u2l, g_u2l);
    cudaGetSymbolAddress((void**)&wph, g_wph);
    cudaGetSymbolAddress((void**)&wpl, g_wpl);
    cudaGetSymbolAddress((void**)&wih, g_wih);
    cudaGetSymbolAddress((void**)&wil, g_wil);
    cudaGetSymbolAddress((void**)&woh, g_woh);
    cudaGetSymbolAddress((void**)&wol, g_wol);

    const float* x_prefix   = (const float*)d_in[0];
    const float* y_aux      = (const float*)d_in[1];
    const float* pre_conv_w = (const float*)d_in[2];
    const float* pre_conv_b = (const float*)d_in[3];
    const float* patch_w    = (const float*)d_in[4];
    const float* patch_b    = (const float*)d_in[5];
    const float* mask_token = (const float*)d_in[6];
    const float* aux_w      = (const float*)d_in[7];
    const float* aux_b      = (const float*)d_in[8];

    const float *patch_out_w, *patch_out_b;
    int fbase, bbase;
    if (n_in > 9 && in_sizes[9] == 65536) {
        patch_out_w = (const float*)d_in[9];
        patch_out_b = (const float*)d_in[10];
        fbase = 11; bbase = 20;
    } else {
        fbase = 9; bbase = 18;
        patch_out_w = (const float*)d_in[27];
        patch_out_b = (const float*)d_in[28];
    }
    const float* fW[9]; const float* bW[9];
    for (int i = 0; i < 9; i++) { fW[i] = (const float*)d_in[fbase+i]; bW[i] = (const float*)d_in[bbase+i]; }

    cudaFuncSetAttribute(k_mmagemm512<0>, cudaFuncAttributeMaxDynamicSharedMemorySize, 2*BUF2_SZ);
    cudaFuncSetAttribute(k_mmagemm512<1>, cudaFuncAttributeMaxDynamicSharedMemorySize, 2*BUF2_SZ);
    cudaFuncSetAttribute(k_mmagemm64, cudaFuncAttributeMaxDynamicSharedMemorySize, 2*BUF_SZ);

    // stage 0
    k_aux<<<1, 256>>>(y_aux, aux_w, aux_b, aux);
    k_preconv<<<MPATCH, 256>>>(x_prefix, pre_conv_w, pre_conv_b, pch, pcl);
    k_cvt_patchw<<<(DM*KPATCH)/256, 256>>>(patch_w, wph, wpl);
    k_cvt_wT<<<dim3((NPADI*DM)/256, 1, 4), 256>>>(fW[1], bW[1], wih, wil, DM, DPROJ, NPADI);
    k_cvt_wT<<<dim3((DM*DIN)/256, 1, 4), 256>>>(fW[8], bW[8], woh, wol, DIN, DM, DM);

    // patch GEMM: split-K=4 partials, then reduce(+bias+aux) -> hf
    k_mmagemm512<0><<<dim3(DM/128, MPATCH/128, KSPLIT), 512, 2*BUF2_SZ>>>(
        pch, pcl, wph, wpl, wph, wpl, pp, KPATCH/KSPLIT, KPATCH, DM, DM);
    k_patchreduce<<<(MPATCH*DM)/256, 256>>>(pp, patch_b, aux, hf);
    k_maskfill<<<(BB*TBWD*DM + 255)/256, 256>>>(mask_token, aux, hf, hb);

    for (int lay = 0; lay < 2; lay++) {
        k_rmsnorm2<<<MTOT, DM>>>(hf, hb, fW[0] + lay*DM, bW[0] + lay*DM, uh, ul);
        // inproj: [5120 x 1152pad], K=256
        k_mmagemm512<1><<<dim3(NPADI/128, MTOT/128, 1), 512, 2*BUF2_SZ>>>(
            uh, ul,
            wih + (size_t)lay*NPADI*DM,     wil + (size_t)lay*NPADI*DM,
            wih + (size_t)(2+lay)*NPADI*DM, wil + (size_t)(2+lay)*NPADI*DM,
            zx, DM, DM, DPROJ, DPROJ);
        k_convdt2<<<MTOT, CONVDIM>>>(zx,
            fW[2] + lay*CONVDIM*4, fW[3] + lay*CONVDIM, fW[4] + lay*NH,
            bW[2] + lay*CONVDIM*4, bW[3] + lay*CONVDIM, bW[4] + lay*NH,
            X, Bbuf, Cbuf, dt);
        k_scan3<<<128, 512>>>(X, Bbuf, Cbuf, dt,
            fW[5] + lay*NH, fW[6] + lay*NH, bW[5] + lay*NH, bW[6] + lay*NH);
        k_gatednorm2<<<MTOT, DIN>>>(Y, zx, fW[7] + lay*DIN, bW[7] + lay*DIN, u2h, u2l);
        // outproj: [5120 x 256], K=512, residual accumulate, split hf/hb
        k_mmagemm64<<<dim3(DM/64, MTOT/128), 256, 2*BUF_SZ>>>(
            u2h, u2l,
            woh + (size_t)lay*DM*DIN,     wol + (size_t)lay*DM*DIN,
            woh + (size_t)(2+lay)*DM*DIN, wol + (size_t)(2+lay)*DM*DIN,
            hf, hb, DIN);
    }

    k_final<<<BB*TBWD, 128>>>(hf, hb, patch_out_w, patch_out_b, (float*)d_out);
    (void)in_sizes; (void)n_in; (void)out_size;
}